// round 4
// baseline (speedup 1.0000x reference)
#include <cuda_runtime.h>
#include <math.h>

#define NBATCH   8
#define NSAMPLES 2048
#define DIMX     4
#define NHID     64
#define NLAYERS  3
#define NN       (NBATCH * NSAMPLES)     // 16384 nodes
#define EE       (NN * 16)               // 262144 edges
#define EPSI     1e-5f

// ---------------- static device scratch (no allocations allowed) ----------------
__device__ float g_h[NN * NHID];          // node features (4 MB)
__device__ float g_agg[NN * NHID];        // message aggregation (4 MB)
__device__ __align__(16) float g_X[NN * DIMX];  // decoded output
__device__ int   g_src[EE];
__device__ int   g_tgt[EE];
__device__ float g_t2[NBATCH];
__device__ float g_t3[NBATCH];

// ---------------- shared-memory layout for the fused MLP kernels ----------------
// W1T: [64 out][128 in] padded stride 132  -> 8448 floats
// W2T: [64 out][64 in]  padded stride 68   -> 4352 floats
// B1, B2: 64 each; IN: 8 warps * 256 floats
#define OFF_W2T 8448
#define OFF_B1  12800
#define OFF_B2  12864
#define OFF_IN  12928
#define SMEM_FLOATS (OFF_IN + 8 * 256)
#define SMEM_BYTES  (SMEM_FLOATS * 4)     // 59904 B

// ---------------- edge index decode (handles int32 or int64 storage) ----------------
__global__ void cvt_edges_kernel(const int* __restrict__ raw) {
    __shared__ int is64;
    if (threadIdx.x == 0) {
        int odd = 0;
        #pragma unroll 1
        for (int i = 1; i < 512; i += 2) odd |= raw[i];
        is64 = (odd == 0) ? 1 : 0;   // int64 little-endian: hi words of small values are 0
    }
    __syncthreads();
    int e = blockIdx.x * blockDim.x + threadIdx.x;
    if (e < EE) {
        if (is64) { g_src[e] = raw[2 * e];        g_tgt[e] = raw[2 * (EE + e)]; }
        else      { g_src[e] = raw[e];            g_tgt[e] = raw[EE + e]; }
    }
}

// ---------------- encoder: h = x @ enc_w + enc_b ; also zero agg ----------------
__global__ void enc_kernel(const float* __restrict__ x,
                           const float* __restrict__ w,
                           const float* __restrict__ b) {
    int tid = blockIdx.x * blockDim.x + threadIdx.x;   // NN*64 threads
    int i = tid >> 6, f = tid & 63;
    float acc = b[f];
    #pragma unroll
    for (int k = 0; k < 4; k++) acc = fmaf(x[i * 4 + k], w[k * 64 + f], acc);
    g_h[tid] = acc;
    g_agg[tid] = 0.f;
}

// ---------------- shared weight staging (transpose + pad) ----------------
__device__ __forceinline__ void stage_weights(float* sm,
                                              const float* __restrict__ w1,
                                              const float* __restrict__ b1,
                                              const float* __restrict__ w2,
                                              const float* __restrict__ b2) {
    int tid = threadIdx.x;
    for (int idx = tid; idx < 128 * 64; idx += 256) {
        int k = idx >> 6, f = idx & 63;
        sm[f * 132 + k] = w1[idx];
    }
    for (int idx = tid; idx < 64 * 64; idx += 256) {
        int k = idx >> 6, f = idx & 63;
        sm[OFF_W2T + f * 68 + k] = w2[idx];
    }
    if (tid < 64) { sm[OFF_B1 + tid] = b1[tid]; sm[OFF_B2 + tid] = b2[tid]; }
    __syncthreads();
}

// ---------------- 2-layer MLP on two 128-wide inputs held in per-warp smem ----------------
// in[0..127]   = input of item A ; in[128..255] = input of item B
// outputs: (c00,c01) = item A features (lane, lane+32); (c10,c11) = item B
__device__ __forceinline__ void mlp2(const float* sm, float* in, int lane,
                                     float& c00, float& c01, float& c10, float& c11) {
    const float4* iA = (const float4*)(in);
    const float4* iB = (const float4*)(in + 128);
    const float4* wA = (const float4*)(sm + lane * 132);
    const float4* wB = (const float4*)(sm + (lane + 32) * 132);
    float a00 = sm[OFF_B1 + lane], a01 = sm[OFF_B1 + lane + 32];
    float a10 = a00, a11 = a01;
    #pragma unroll
    for (int k4 = 0; k4 < 32; k4++) {
        float4 ia = iA[k4], ib = iB[k4], wa = wA[k4], wb = wB[k4];
        a00 = fmaf(ia.x, wa.x, a00); a00 = fmaf(ia.y, wa.y, a00);
        a00 = fmaf(ia.z, wa.z, a00); a00 = fmaf(ia.w, wa.w, a00);
        a01 = fmaf(ia.x, wb.x, a01); a01 = fmaf(ia.y, wb.y, a01);
        a01 = fmaf(ia.z, wb.z, a01); a01 = fmaf(ia.w, wb.w, a01);
        a10 = fmaf(ib.x, wa.x, a10); a10 = fmaf(ib.y, wa.y, a10);
        a10 = fmaf(ib.z, wa.z, a10); a10 = fmaf(ib.w, wa.w, a10);
        a11 = fmaf(ib.x, wb.x, a11); a11 = fmaf(ib.y, wb.y, a11);
        a11 = fmaf(ib.z, wb.z, a11); a11 = fmaf(ib.w, wb.w, a11);
    }
    a00 = fmaxf(a00, 0.f); a01 = fmaxf(a01, 0.f);
    a10 = fmaxf(a10, 0.f); a11 = fmaxf(a11, 0.f);
    __syncwarp();
    in[lane] = a00; in[lane + 32] = a01;
    in[128 + lane] = a10; in[160 + lane] = a11;
    __syncwarp();
    const float4* w2A = (const float4*)(sm + OFF_W2T + lane * 68);
    const float4* w2B = (const float4*)(sm + OFF_W2T + (lane + 32) * 68);
    c00 = sm[OFF_B2 + lane]; c01 = sm[OFF_B2 + lane + 32];
    c10 = c00; c11 = c01;
    #pragma unroll
    for (int k4 = 0; k4 < 16; k4++) {
        float4 ia = iA[k4], ib = iB[k4], wa = w2A[k4], wb = w2B[k4];
        c00 = fmaf(ia.x, wa.x, c00); c00 = fmaf(ia.y, wa.y, c00);
        c00 = fmaf(ia.z, wa.z, c00); c00 = fmaf(ia.w, wa.w, c00);
        c01 = fmaf(ia.x, wb.x, c01); c01 = fmaf(ia.y, wb.y, c01);
        c01 = fmaf(ia.z, wb.z, c01); c01 = fmaf(ia.w, wb.w, c01);
        c10 = fmaf(ib.x, wa.x, c10); c10 = fmaf(ib.y, wa.y, c10);
        c10 = fmaf(ib.z, wa.z, c10); c10 = fmaf(ib.w, wa.w, c10);
        c11 = fmaf(ib.x, wb.x, c11); c11 = fmaf(ib.y, wb.y, c11);
        c11 = fmaf(ib.z, wb.z, c11); c11 = fmaf(ib.w, wb.w, c11);
    }
    c00 = fmaxf(c00, 0.f); c01 = fmaxf(c01, 0.f);
    c10 = fmaxf(c10, 0.f); c11 = fmaxf(c11, 0.f);
}

// ---------------- edge message kernel: m = MLP([h[tgt], h[src]]) ; agg[tgt] += m ----------------
#define EPW 8   // edges per warp
__global__ void __launch_bounds__(256) edge_kernel(const float* __restrict__ w1,
                                                   const float* __restrict__ b1,
                                                   const float* __restrict__ w2,
                                                   const float* __restrict__ b2) {
    extern __shared__ float sm[];
    stage_weights(sm, w1, b1, w2, b2);
    int tid = threadIdx.x, warp = tid >> 5, lane = tid & 31;
    float* in = sm + OFF_IN + warp * 256;
    int ebase = (blockIdx.x * 8 + warp) * EPW;
    #pragma unroll 1
    for (int p = 0; p < EPW; p += 2) {
        int e0 = ebase + p, e1 = e0 + 1;
        int t0 = g_tgt[e0], s0 = g_src[e0];
        int t1 = g_tgt[e1], s1 = g_src[e1];
        const float* ht0 = &g_h[t0 * 64]; const float* hs0 = &g_h[s0 * 64];
        const float* ht1 = &g_h[t1 * 64]; const float* hs1 = &g_h[s1 * 64];
        in[lane]       = ht0[lane]; in[lane + 32]  = ht0[lane + 32];
        in[lane + 64]  = hs0[lane]; in[lane + 96]  = hs0[lane + 32];
        in[128 + lane] = ht1[lane]; in[160 + lane] = ht1[lane + 32];
        in[192 + lane] = hs1[lane]; in[224 + lane] = hs1[lane + 32];
        __syncwarp();
        float c00, c01, c10, c11;
        mlp2(sm, in, lane, c00, c01, c10, c11);
        atomicAdd(&g_agg[t0 * 64 + lane],      c00);
        atomicAdd(&g_agg[t0 * 64 + lane + 32], c01);
        atomicAdd(&g_agg[t1 * 64 + lane],      c10);
        atomicAdd(&g_agg[t1 * 64 + lane + 32], c11);
        __syncwarp();
    }
}

// ---------------- node update kernel: h = MLP([h, agg]) ; zero agg for next layer ----------------
#define NPW 4   // nodes per warp
__global__ void __launch_bounds__(256) upd_kernel(const float* __restrict__ w1,
                                                  const float* __restrict__ b1,
                                                  const float* __restrict__ w2,
                                                  const float* __restrict__ b2) {
    extern __shared__ float sm[];
    stage_weights(sm, w1, b1, w2, b2);
    int tid = threadIdx.x, warp = tid >> 5, lane = tid & 31;
    float* in = sm + OFF_IN + warp * 256;
    int nbase = (blockIdx.x * 8 + warp) * NPW;
    #pragma unroll 1
    for (int p = 0; p < NPW; p += 2) {
        int n0 = nbase + p, n1 = n0 + 1;
        in[lane]       = g_h[n0 * 64 + lane];   in[lane + 32]  = g_h[n0 * 64 + lane + 32];
        in[lane + 64]  = g_agg[n0 * 64 + lane]; in[lane + 96]  = g_agg[n0 * 64 + lane + 32];
        in[128 + lane] = g_h[n1 * 64 + lane];   in[160 + lane] = g_h[n1 * 64 + lane + 32];
        in[192 + lane] = g_agg[n1 * 64 + lane]; in[224 + lane] = g_agg[n1 * 64 + lane + 32];
        g_agg[n0 * 64 + lane] = 0.f; g_agg[n0 * 64 + lane + 32] = 0.f;
        g_agg[n1 * 64 + lane] = 0.f; g_agg[n1 * 64 + lane + 32] = 0.f;
        __syncwarp();
        float c00, c01, c10, c11;
        mlp2(sm, in, lane, c00, c01, c10, c11);
        g_h[n0 * 64 + lane]      = c00;
        g_h[n0 * 64 + lane + 32] = c01;
        g_h[n1 * 64 + lane]      = c10;
        g_h[n1 * 64 + lane + 32] = c11;
        __syncwarp();
    }
}

// ---------------- per-graph instance norm (two-pass, values in registers) ----------------
__global__ void norm_kernel() {
    int g = blockIdx.x >> 6;
    int f = blockIdx.x & 63;
    int tid = threadIdx.x;              // 256
    int base = (g * NSAMPLES) * 64 + f;
    float v[8];
    #pragma unroll
    for (int r = 0; r < 8; r++) v[r] = g_h[base + (tid + r * 256) * 64];
    __shared__ float red[256];
    __shared__ float s_mean, s_rstd;
    float s = 0.f;
    #pragma unroll
    for (int r = 0; r < 8; r++) s += v[r];
    red[tid] = s; __syncthreads();
    for (int off = 128; off > 0; off >>= 1) {
        if (tid < off) red[tid] += red[tid + off];
        __syncthreads();
    }
    if (tid == 0) s_mean = red[0] * (1.f / NSAMPLES);
    __syncthreads();
    float mean = s_mean;
    float q = 0.f;
    #pragma unroll
    for (int r = 0; r < 8; r++) { float d = v[r] - mean; q = fmaf(d, d, q); }
    red[tid] = q; __syncthreads();
    for (int off = 128; off > 0; off >>= 1) {
        if (tid < off) red[tid] += red[tid + off];
        __syncthreads();
    }
    if (tid == 0) s_rstd = rsqrtf(red[0] * (1.f / NSAMPLES) + EPSI);
    __syncthreads();
    float rstd = s_rstd;
    #pragma unroll
    for (int r = 0; r < 8; r++)
        g_h[base + (tid + r * 256) * 64] = (v[r] - mean) * rstd;
}

__global__ void zero_small_kernel() {
    int t = threadIdx.x;
    if (t < NBATCH) { g_t2[t] = 0.f; g_t3[t] = 0.f; }
}

// ---------------- decoder + t2 term ----------------
__global__ void dec_kernel(const float* __restrict__ w, const float* __restrict__ b) {
    int i = blockIdx.x * blockDim.x + threadIdx.x;   // NN threads
    const float* hr = &g_h[i * 64];
    float a0 = b[0], a1 = b[1], a2 = b[2], a3 = b[3];
    #pragma unroll 8
    for (int k = 0; k < 64; k++) {
        float hv = hr[k];
        a0 = fmaf(hv, w[k * 4 + 0], a0);
        a1 = fmaf(hv, w[k * 4 + 1], a1);
        a2 = fmaf(hv, w[k * 4 + 2], a2);
        a3 = fmaf(hv, w[k * 4 + 3], a3);
    }
    a0 = 1.f / (1.f + expf(-a0));
    a1 = 1.f / (1.f + expf(-a1));
    a2 = 1.f / (1.f + expf(-a2));
    a3 = 1.f / (1.f + expf(-a3));
    g_X[i * 4 + 0] = a0; g_X[i * 4 + 1] = a1;
    g_X[i * 4 + 2] = a2; g_X[i * 4 + 3] = a3;
    float pr = (1.f - a0 * a0) * (1.f - a1 * a1) * (1.f - a2 * a2) * (1.f - a3 * a3);
    #pragma unroll
    for (int off = 16; off > 0; off >>= 1)
        pr += __shfl_down_sync(0xffffffffu, pr, off);
    if ((threadIdx.x & 31) == 0) atomicAdd(&g_t2[i >> 11], pr);
}

// ---------------- t3 pairwise term ----------------
__global__ void t3_kernel() {
    int b = blockIdx.x;            // 512 blocks: 8 graphs x 16 i-chunks x 4 j-chunks
    int g = b >> 6, ic = (b >> 2) & 15, jc = b & 3;
    int tid = threadIdx.x;         // 128
    __shared__ float4 sX[512];
    const float4* Xg = (const float4*)&g_X[(g * NSAMPLES) * 4];
    for (int j = tid; j < 512; j += 128) sX[j] = Xg[jc * 512 + j];
    __syncthreads();
    float4 xi = Xg[ic * 128 + tid];
    float acc = 0.f;
    #pragma unroll 4
    for (int j = 0; j < 512; j++) {
        float4 xj = sX[j];
        float p = (1.f - fmaxf(xi.x, xj.x)) * (1.f - fmaxf(xi.y, xj.y)) *
                  (1.f - fmaxf(xi.z, xj.z)) * (1.f - fmaxf(xi.w, xj.w));
        acc += p;
    }
    __shared__ float red[128];
    red[tid] = acc; __syncthreads();
    for (int off = 64; off > 0; off >>= 1) {
        if (tid < off) red[tid] += red[tid + off];
        __syncthreads();
    }
    if (tid == 0) atomicAdd(&g_t3[g], red[0]);
}

// ---------------- emit: loss + X into d_out ----------------
__global__ void emit_kernel(float* __restrict__ out, int out_size) {
    int tid = blockIdx.x * blockDim.x + threadIdx.x;
    float loss = 0.f;
    if (tid == 0) {
        const float t1 = 1.0f / 81.0f;             // (1/3)^4
        #pragma unroll
        for (int g = 0; g < NBATCH; g++) {
            float l = t1 - g_t2[g] * (2.0f / 32768.0f)
                         + g_t3[g] * (1.0f / (2048.f * 2048.f));
            loss += l;
        }
        loss *= (1.0f / NBATCH);
    }
    if (out_size == NN * DIMX) {                   // X only
        if (tid < NN * DIMX) out[tid] = g_X[tid];
    } else {                                       // [loss, X...]
        if (tid == 0) out[0] = loss;
        int idx = tid - 1;
        if (idx >= 0 && idx < NN * DIMX && (idx + 1) < out_size) out[1 + idx] = g_X[idx];
    }
}

// ---------------- launch ----------------
extern "C" void kernel_launch(void* const* d_in, const int* in_sizes, int n_in,
                              void* d_out, int out_size) {
    const float* x     = (const float*)d_in[0];
    const int*   eiraw = (const int*)  d_in[1];
    const float* enc_w = (const float*)d_in[2];
    const float* enc_b = (const float*)d_in[3];
    const float* m1_w  = (const float*)d_in[4];
    const float* m1_b  = (const float*)d_in[5];
    const float* m2_w  = (const float*)d_in[6];
    const float* m2_b  = (const float*)d_in[7];
    const float* u1_w  = (const float*)d_in[8];
    const float* u1_b  = (const float*)d_in[9];
    const float* u2_w  = (const float*)d_in[10];
    const float* u2_b  = (const float*)d_in[11];
    const float* dec_w = (const float*)d_in[12];
    const float* dec_b = (const float*)d_in[13];
    float* out = (float*)d_out;

    (void)cudaFuncSetAttribute(edge_kernel, cudaFuncAttributeMaxDynamicSharedMemorySize, SMEM_BYTES);
    (void)cudaFuncSetAttribute(upd_kernel,  cudaFuncAttributeMaxDynamicSharedMemorySize, SMEM_BYTES);

    cvt_edges_kernel<<<(EE + 255) / 256, 256>>>(eiraw);
    enc_kernel<<<NN * NHID / 256, 256>>>(x, enc_w, enc_b);
    for (int l = 0; l < NLAYERS; l++) {
        edge_kernel<<<EE / (8 * EPW), 256, SMEM_BYTES>>>(
            m1_w + l * 128 * 64, m1_b + l * 64, m2_w + l * 64 * 64, m2_b + l * 64);
        upd_kernel<<<NN / (8 * NPW), 256, SMEM_BYTES>>>(
            u1_w + l * 128 * 64, u1_b + l * 64, u2_w + l * 64 * 64, u2_b + l * 64);
        norm_kernel<<<NBATCH * NHID, 256>>>();
    }
    zero_small_kernel<<<1, 32>>>();
    dec_kernel<<<NN / 256, 256>>>(dec_w, dec_b);
    t3_kernel<<<512, 128>>>();
    emit_kernel<<<(NN * DIMX + 1 + 255) / 256, 256>>>(out, out_size);
}

// round 6
// speedup vs baseline: 1.8473x; 1.8473x over previous
#include <cuda_runtime.h>
#include <math.h>
#include <stdint.h>

#define NBATCH   8
#define NSAMPLES 2048
#define DIMX     4
#define NHID     64
#define NLAYERS  3
#define NN       (NBATCH * NSAMPLES)     // 16384 nodes
#define EE       (NN * 16)               // 262144 edges
#define EPSI     1e-5f

// ---------------- static device scratch (no allocations allowed) ----------------
__device__ float g_h[NN * NHID];          // node features (4 MB)
__device__ float g_agg[NN * NHID];        // message aggregation (4 MB)
__device__ __align__(16) float g_X[NN * DIMX];  // decoded output
__device__ int   g_src[EE];
__device__ int   g_tgt[EE];
__device__ float g_t2[NBATCH];
__device__ float g_t3[NBATCH];

// ---------------- shared memory layout for the MMA kernels (floats) ----------------
// sA : 64 rows x 132 (pad)  = 8448   (input tile, fp32)
// sB1: 128 x 72 (pad)       = 9216   (W1, k-major)
// sM : 64 x 68 (pad)        = 4352   (intermediate relu'd activations)
// sB2: 64 x 72 (pad)        = 4608   (W2, k-major)
#define OFF_A   0
#define OFF_B1  8448
#define OFF_M   17664
#define OFF_B2  22016
#define SMEM_MMA_FLOATS 26624
#define SMEM_MMA_BYTES  (SMEM_MMA_FLOATS * 4)   // 106496 B -> 2 blocks/SM

// ---------------- tf32 helpers ----------------
__device__ __forceinline__ void split_tf32(float x, uint32_t& hi, uint32_t& lo) {
    uint32_t h;
    asm("cvt.rna.tf32.f32 %0, %1;" : "=r"(h) : "f"(x));
    float l = x - __uint_as_float(h);
    uint32_t lr;
    asm("cvt.rna.tf32.f32 %0, %1;" : "=r"(lr) : "f"(l));
    hi = h; lo = lr;
}

__device__ __forceinline__ void mma_tf32(float c[4], const uint32_t a[4], const uint32_t b[2]) {
    asm volatile(
        "mma.sync.aligned.m16n8k8.row.col.f32.tf32.tf32.f32 "
        "{%0,%1,%2,%3}, {%4,%5,%6,%7}, {%8,%9}, {%0,%1,%2,%3};"
        : "+f"(c[0]), "+f"(c[1]), "+f"(c[2]), "+f"(c[3])
        : "r"(a[0]), "r"(a[1]), "r"(a[2]), "r"(a[3]), "r"(b[0]), "r"(b[1]));
}

// warp computes a 16(m) x 32(n) tile: acc[nt][4], nt over 4 n-frags of 8.
// A: sA[row*LDA + k] (row-major, m x K). B: sB[k*LDB + n] (k-major, K x 64).
// 3xTF32: acc += Ahi*Bhi + Ahi*Blo + Alo*Bhi  (near-fp32 accuracy)
template<int K, int LDA, int LDB>
__device__ __forceinline__ void gemm_warp(const float* __restrict__ sA,
                                          const float* __restrict__ sB,
                                          int me, int n0, int lane, float acc[4][4]) {
    int gid = lane >> 2, tig = lane & 3;
    #pragma unroll
    for (int k0 = 0; k0 < K; k0 += 8) {
        float af0 = sA[(me + gid) * LDA + k0 + tig];
        float af1 = sA[(me + gid + 8) * LDA + k0 + tig];
        float af2 = sA[(me + gid) * LDA + k0 + tig + 4];
        float af3 = sA[(me + gid + 8) * LDA + k0 + tig + 4];
        uint32_t ah[4], al[4];
        split_tf32(af0, ah[0], al[0]);
        split_tf32(af1, ah[1], al[1]);
        split_tf32(af2, ah[2], al[2]);
        split_tf32(af3, ah[3], al[3]);
        #pragma unroll
        for (int nt = 0; nt < 4; nt++) {
            float b0f = sB[(k0 + tig) * LDB + n0 + nt * 8 + gid];
            float b1f = sB[(k0 + tig + 4) * LDB + n0 + nt * 8 + gid];
            uint32_t bh[2], bl[2];
            split_tf32(b0f, bh[0], bl[0]);
            split_tf32(b1f, bh[1], bl[1]);
            mma_tf32(acc[nt], al, bh);
            mma_tf32(acc[nt], ah, bl);
            mma_tf32(acc[nt], ah, bh);
        }
    }
}

// ---------------- edge index decode (handles int32 or int64 storage) ----------------
__global__ void cvt_edges_kernel(const int* __restrict__ raw) {
    __shared__ int is64;
    if (threadIdx.x == 0) {
        int odd = 0;
        #pragma unroll 1
        for (int i = 1; i < 512; i += 2) odd |= raw[i];
        is64 = (odd == 0) ? 1 : 0;   // int64 little-endian: hi words of small values are 0
    }
    __syncthreads();
    int e = blockIdx.x * blockDim.x + threadIdx.x;
    if (e < EE) {
        if (is64) { g_src[e] = raw[2 * e];        g_tgt[e] = raw[2 * (EE + e)]; }
        else      { g_src[e] = raw[e];            g_tgt[e] = raw[EE + e]; }
    }
}

// ---------------- encoder: h = x @ enc_w + enc_b ; also zero agg ----------------
__global__ void enc_kernel(const float* __restrict__ x,
                           const float* __restrict__ w,
                           const float* __restrict__ b) {
    int tid = blockIdx.x * blockDim.x + threadIdx.x;   // NN*64 threads
    int i = tid >> 6, f = tid & 63;
    float acc = b[f];
    #pragma unroll
    for (int k = 0; k < 4; k++) acc = fmaf(x[i * 4 + k], w[k * 64 + f], acc);
    g_h[tid] = acc;
    g_agg[tid] = 0.f;
}

// ---------------- edge message kernel (tensor core) ----------------
// block: 64 edges. A = [h[tgt] | h[src]] (64x128). GEMM1 relu -> GEMM2 relu -> scatter add.
__global__ void __launch_bounds__(256) edge_mma_kernel(const float* __restrict__ w1,
                                                       const float* __restrict__ b1,
                                                       const float* __restrict__ w2,
                                                       const float* __restrict__ b2) {
    extern __shared__ float sm[];
    float* sA  = sm + OFF_A;
    float* sB1 = sm + OFF_B1;
    float* sM  = sm + OFF_M;
    float* sB2 = sm + OFF_B2;
    int tid = threadIdx.x;
    int e0 = blockIdx.x * 64;

    // gather A tile: 64 edges x 128 feats (tgt feats cols 0-63, src feats cols 64-127)
    #pragma unroll
    for (int it = 0; it < 8; it++) {
        int i = tid + it * 256;           // 2048 float4s
        int e = i >> 5, part = i & 31;
        int node = (part < 16) ? g_tgt[e0 + e] : g_src[e0 + e];
        float4 v = *(const float4*)&g_h[node * 64 + (part & 15) * 4];
        *(float4*)&sA[e * 132 + part * 4] = v;
    }
    // stage weights (k-major with pad 72)
    #pragma unroll 4
    for (int i = tid; i < 8192; i += 256) sB1[(i >> 6) * 72 + (i & 63)] = w1[i];
    #pragma unroll 4
    for (int i = tid; i < 4096; i += 256) sB2[(i >> 6) * 72 + (i & 63)] = w2[i];
    __syncthreads();

    int warp = tid >> 5, lane = tid & 31, gid = lane >> 2, tig = lane & 3;
    int me = (warp >> 1) * 16, n0 = (warp & 1) * 32;

    float acc[4][4] = {};
    gemm_warp<128, 132, 72>(sA, sB1, me, n0, lane, acc);
    #pragma unroll
    for (int nt = 0; nt < 4; nt++) {
        int col = n0 + nt * 8 + 2 * tig;
        float bb0 = __ldg(b1 + col), bb1 = __ldg(b1 + col + 1);
        sM[(me + gid) * 68 + col]       = fmaxf(acc[nt][0] + bb0, 0.f);
        sM[(me + gid) * 68 + col + 1]   = fmaxf(acc[nt][1] + bb1, 0.f);
        sM[(me + gid + 8) * 68 + col]     = fmaxf(acc[nt][2] + bb0, 0.f);
        sM[(me + gid + 8) * 68 + col + 1] = fmaxf(acc[nt][3] + bb1, 0.f);
    }
    __syncthreads();

    float acc2[4][4] = {};
    gemm_warp<64, 68, 72>(sM, sB2, me, n0, lane, acc2);
    int t0 = g_tgt[e0 + me + gid];
    int t1 = g_tgt[e0 + me + gid + 8];
    #pragma unroll
    for (int nt = 0; nt < 4; nt++) {
        int col = n0 + nt * 8 + 2 * tig;
        float bb0 = __ldg(b2 + col), bb1 = __ldg(b2 + col + 1);
        atomicAdd(&g_agg[t0 * 64 + col],     fmaxf(acc2[nt][0] + bb0, 0.f));
        atomicAdd(&g_agg[t0 * 64 + col + 1], fmaxf(acc2[nt][1] + bb1, 0.f));
        atomicAdd(&g_agg[t1 * 64 + col],     fmaxf(acc2[nt][2] + bb0, 0.f));
        atomicAdd(&g_agg[t1 * 64 + col + 1], fmaxf(acc2[nt][3] + bb1, 0.f));
    }
}

// ---------------- node update kernel (tensor core) ----------------
// block: 64 nodes. A = [h | agg] (64x128). GEMM1 relu -> GEMM2 relu -> write h; zero agg.
__global__ void __launch_bounds__(256) upd_mma_kernel(const float* __restrict__ w1,
                                                      const float* __restrict__ b1,
                                                      const float* __restrict__ w2,
                                                      const float* __restrict__ b2) {
    extern __shared__ float sm[];
    float* sA  = sm + OFF_A;
    float* sB1 = sm + OFF_B1;
    float* sM  = sm + OFF_M;
    float* sB2 = sm + OFF_B2;
    int tid = threadIdx.x;
    int nb0 = blockIdx.x * 64;

    #pragma unroll
    for (int it = 0; it < 8; it++) {
        int i = tid + it * 256;
        int e = i >> 5, part = i & 31;
        int node = nb0 + e;
        float4 v;
        if (part < 16) {
            v = *(const float4*)&g_h[node * 64 + part * 4];
        } else {
            float4* ap = (float4*)&g_agg[node * 64 + (part & 15) * 4];
            v = *ap;
            *ap = make_float4(0.f, 0.f, 0.f, 0.f);   // reset for next layer
        }
        *(float4*)&sA[e * 132 + part * 4] = v;
    }
    #pragma unroll 4
    for (int i = tid; i < 8192; i += 256) sB1[(i >> 6) * 72 + (i & 63)] = w1[i];
    #pragma unroll 4
    for (int i = tid; i < 4096; i += 256) sB2[(i >> 6) * 72 + (i & 63)] = w2[i];
    __syncthreads();

    int warp = tid >> 5, lane = tid & 31, gid = lane >> 2, tig = lane & 3;
    int me = (warp >> 1) * 16, n0 = (warp & 1) * 32;

    float acc[4][4] = {};
    gemm_warp<128, 132, 72>(sA, sB1, me, n0, lane, acc);
    #pragma unroll
    for (int nt = 0; nt < 4; nt++) {
        int col = n0 + nt * 8 + 2 * tig;
        float bb0 = __ldg(b1 + col), bb1 = __ldg(b1 + col + 1);
        sM[(me + gid) * 68 + col]       = fmaxf(acc[nt][0] + bb0, 0.f);
        sM[(me + gid) * 68 + col + 1]   = fmaxf(acc[nt][1] + bb1, 0.f);
        sM[(me + gid + 8) * 68 + col]     = fmaxf(acc[nt][2] + bb0, 0.f);
        sM[(me + gid + 8) * 68 + col + 1] = fmaxf(acc[nt][3] + bb1, 0.f);
    }
    __syncthreads();

    float acc2[4][4] = {};
    gemm_warp<64, 68, 72>(sM, sB2, me, n0, lane, acc2);
    int r0 = nb0 + me + gid, r1 = nb0 + me + gid + 8;
    #pragma unroll
    for (int nt = 0; nt < 4; nt++) {
        int col = n0 + nt * 8 + 2 * tig;
        float bb0 = __ldg(b2 + col), bb1 = __ldg(b2 + col + 1);
        g_h[r0 * 64 + col]     = fmaxf(acc2[nt][0] + bb0, 0.f);
        g_h[r0 * 64 + col + 1] = fmaxf(acc2[nt][1] + bb1, 0.f);
        g_h[r1 * 64 + col]     = fmaxf(acc2[nt][2] + bb0, 0.f);
        g_h[r1 * 64 + col + 1] = fmaxf(acc2[nt][3] + bb1, 0.f);
    }
}

// ---------------- per-graph instance norm (two-pass, values in registers) ----------------
__global__ void norm_kernel() {
    int g = blockIdx.x >> 6;
    int f = blockIdx.x & 63;
    int tid = threadIdx.x;              // 256
    int base = (g * NSAMPLES) * 64 + f;
    float v[8];
    #pragma unroll
    for (int r = 0; r < 8; r++) v[r] = g_h[base + (tid + r * 256) * 64];
    __shared__ float red[256];
    __shared__ float s_mean, s_rstd;
    float s = 0.f;
    #pragma unroll
    for (int r = 0; r < 8; r++) s += v[r];
    red[tid] = s; __syncthreads();
    for (int off = 128; off > 0; off >>= 1) {
        if (tid < off) red[tid] += red[tid + off];
        __syncthreads();
    }
    if (tid == 0) s_mean = red[0] * (1.f / NSAMPLES);
    __syncthreads();
    float mean = s_mean;
    float q = 0.f;
    #pragma unroll
    for (int r = 0; r < 8; r++) { float d = v[r] - mean; q = fmaf(d, d, q); }
    red[tid] = q; __syncthreads();
    for (int off = 128; off > 0; off >>= 1) {
        if (tid < off) red[tid] += red[tid + off];
        __syncthreads();
    }
    if (tid == 0) s_rstd = rsqrtf(red[0] * (1.f / NSAMPLES) + EPSI);
    __syncthreads();
    float rstd = s_rstd;
    #pragma unroll
    for (int r = 0; r < 8; r++)
        g_h[base + (tid + r * 256) * 64] = (v[r] - mean) * rstd;
}

__global__ void zero_small_kernel() {
    int t = threadIdx.x;
    if (t < NBATCH) { g_t2[t] = 0.f; g_t3[t] = 0.f; }
}

// ---------------- decoder + t2 term ----------------
__global__ void dec_kernel(const float* __restrict__ w, const float* __restrict__ b) {
    int i = blockIdx.x * blockDim.x + threadIdx.x;   // NN threads
    const float* hr = &g_h[i * 64];
    float a0 = b[0], a1 = b[1], a2 = b[2], a3 = b[3];
    #pragma unroll 8
    for (int k = 0; k < 64; k++) {
        float hv = hr[k];
        a0 = fmaf(hv, w[k * 4 + 0], a0);
        a1 = fmaf(hv, w[k * 4 + 1], a1);
        a2 = fmaf(hv, w[k * 4 + 2], a2);
        a3 = fmaf(hv, w[k * 4 + 3], a3);
    }
    a0 = 1.f / (1.f + expf(-a0));
    a1 = 1.f / (1.f + expf(-a1));
    a2 = 1.f / (1.f + expf(-a2));
    a3 = 1.f / (1.f + expf(-a3));
    g_X[i * 4 + 0] = a0; g_X[i * 4 + 1] = a1;
    g_X[i * 4 + 2] = a2; g_X[i * 4 + 3] = a3;
    float pr = (1.f - a0 * a0) * (1.f - a1 * a1) * (1.f - a2 * a2) * (1.f - a3 * a3);
    #pragma unroll
    for (int off = 16; off > 0; off >>= 1)
        pr += __shfl_down_sync(0xffffffffu, pr, off);
    if ((threadIdx.x & 31) == 0) atomicAdd(&g_t2[i >> 11], pr);
}

// ---------------- t3 pairwise term ----------------
__global__ void t3_kernel() {
    int b = blockIdx.x;            // 512 blocks: 8 graphs x 16 i-chunks x 4 j-chunks
    int g = b >> 6, ic = (b >> 2) & 15, jc = b & 3;
    int tid = threadIdx.x;         // 128
    __shared__ float4 sX[512];
    const float4* Xg = (const float4*)&g_X[(g * NSAMPLES) * 4];
    for (int j = tid; j < 512; j += 128) sX[j] = Xg[jc * 512 + j];
    __syncthreads();
    float4 xi = Xg[ic * 128 + tid];
    float acc = 0.f;
    #pragma unroll 4
    for (int j = 0; j < 512; j++) {
        float4 xj = sX[j];
        float p = (1.f - fmaxf(xi.x, xj.x)) * (1.f - fmaxf(xi.y, xj.y)) *
                  (1.f - fmaxf(xi.z, xj.z)) * (1.f - fmaxf(xi.w, xj.w));
        acc += p;
    }
    __shared__ float red[128];
    red[tid] = acc; __syncthreads();
    for (int off = 64; off > 0; off >>= 1) {
        if (tid < off) red[tid] += red[tid + off];
        __syncthreads();
    }
    if (tid == 0) atomicAdd(&g_t3[g], red[0]);
}

// ---------------- emit: loss + X into d_out ----------------
__global__ void emit_kernel(float* __restrict__ out, int out_size) {
    int tid = blockIdx.x * blockDim.x + threadIdx.x;
    float loss = 0.f;
    if (tid == 0) {
        const float t1 = 1.0f / 81.0f;             // (1/3)^4
        #pragma unroll
        for (int g = 0; g < NBATCH; g++) {
            float l = t1 - g_t2[g] * (2.0f / 32768.0f)
                         + g_t3[g] * (1.0f / (2048.f * 2048.f));
            loss += l;
        }
        loss *= (1.0f / NBATCH);
    }
    if (out_size == NN * DIMX) {                   // X only
        if (tid < NN * DIMX) out[tid] = g_X[tid];
    } else {                                       // [loss, X...]
        if (tid == 0) out[0] = loss;
        int idx = tid - 1;
        if (idx >= 0 && idx < NN * DIMX && (idx + 1) < out_size) out[1 + idx] = g_X[idx];
    }
}

// ---------------- launch ----------------
extern "C" void kernel_launch(void* const* d_in, const int* in_sizes, int n_in,
                              void* d_out, int out_size) {
    const float* x     = (const float*)d_in[0];
    const int*   eiraw = (const int*)  d_in[1];
    const float* enc_w = (const float*)d_in[2];
    const float* enc_b = (const float*)d_in[3];
    const float* m1_w  = (const float*)d_in[4];
    const float* m1_b  = (const float*)d_in[5];
    const float* m2_w  = (const float*)d_in[6];
    const float* m2_b  = (const float*)d_in[7];
    const float* u1_w  = (const float*)d_in[8];
    const float* u1_b  = (const float*)d_in[9];
    const float* u2_w  = (const float*)d_in[10];
    const float* u2_b  = (const float*)d_in[11];
    const float* dec_w = (const float*)d_in[12];
    const float* dec_b = (const float*)d_in[13];
    float* out = (float*)d_out;

    (void)cudaFuncSetAttribute(edge_mma_kernel, cudaFuncAttributeMaxDynamicSharedMemorySize, SMEM_MMA_BYTES);
    (void)cudaFuncSetAttribute(upd_mma_kernel,  cudaFuncAttributeMaxDynamicSharedMemorySize, SMEM_MMA_BYTES);

    cvt_edges_kernel<<<(EE + 255) / 256, 256>>>(eiraw);
    enc_kernel<<<NN * NHID / 256, 256>>>(x, enc_w, enc_b);
    for (int l = 0; l < NLAYERS; l++) {
        edge_mma_kernel<<<EE / 64, 256, SMEM_MMA_BYTES>>>(
            m1_w + l * 128 * 64, m1_b + l * 64, m2_w + l * 64 * 64, m2_b + l * 64);
        upd_mma_kernel<<<NN / 64, 256, SMEM_MMA_BYTES>>>(
            u1_w + l * 128 * 64, u1_b + l * 64, u2_w + l * 64 * 64, u2_b + l * 64);
        norm_kernel<<<NBATCH * NHID, 256>>>();
    }
    zero_small_kernel<<<1, 32>>>();
    dec_kernel<<<NN / 256, 256>>>(dec_w, dec_b);
    t3_kernel<<<512, 128>>>();
    emit_kernel<<<(NN * DIMX + 1 + 255) / 256, 256>>>(out, out_size);
}

// round 8
// speedup vs baseline: 1.9077x; 1.0327x over previous
#include <cuda_runtime.h>
#include <math.h>
#include <stdint.h>

#define NBATCH   8
#define NSAMPLES 2048
#define DIMX     4
#define NHID     64
#define NLAYERS  3
#define NN       (NBATCH * NSAMPLES)     // 16384 nodes
#define EE       (NN * 16)               // 262144 edges
#define EPSI     1e-5f

// ---------------- static device scratch ----------------
__device__ float g_h[NN * NHID];
__device__ float g_agg[NN * NHID];
__device__ __align__(16) float g_X[NN * DIMX];
__device__ int   g_src[EE];
__device__ int   g_tgt[EE];
__device__ float g_t2[NBATCH];
__device__ float g_t3[NBATCH];
__device__ float g_sum[NBATCH * NHID];   // per-graph per-feature sums
__device__ float g_sqs[NBATCH * NHID];   // per-graph per-feature sum of squares

// ---------------- smem layout for persistent MMA kernels (floats) ----------------
// sA  : 128 x 132           = 16896   (input tile fp32; reused as output staging stride 68)
// sM  : 128 x 68            = 8704    (relu'd intermediate)
// B1hi/B1lo : 128 x 72 each = 9216 x2 (W1 pre-split tf32)
// B2hi/B2lo :  64 x 72 each = 4608 x2 (W2 pre-split tf32)
// bias1, bias2: 64 each
#define OFF_A    0
#define OFF_M    16896
#define OFF_B1H  25600
#define OFF_B1L  34816
#define OFF_B2H  44032
#define OFF_B2L  48640
#define OFF_BI1  53248
#define OFF_BI2  53312
#define SMEM_MMA_FLOATS 53376
#define SMEM_MMA_BYTES  (SMEM_MMA_FLOATS * 4)   // 213504 B -> 1 block/SM

// ---------------- tf32 helpers ----------------
__device__ __forceinline__ void split_tf32(float x, uint32_t& hi, uint32_t& lo) {
    uint32_t h;
    asm("cvt.rna.tf32.f32 %0, %1;" : "=r"(h) : "f"(x));
    float l = x - __uint_as_float(h);
    uint32_t lr;
    asm("cvt.rna.tf32.f32 %0, %1;" : "=r"(lr) : "f"(l));
    hi = h; lo = lr;
}

__device__ __forceinline__ void mma_tf32(float c[4], const uint32_t a[4], const uint32_t b[2]) {
    asm volatile(
        "mma.sync.aligned.m16n8k8.row.col.f32.tf32.tf32.f32 "
        "{%0,%1,%2,%3}, {%4,%5,%6,%7}, {%8,%9}, {%0,%1,%2,%3};"
        : "+f"(c[0]), "+f"(c[1]), "+f"(c[2]), "+f"(c[3])
        : "r"(a[0]), "r"(a[1]), "r"(a[2]), "r"(a[3]), "r"(b[0]), "r"(b[1]));
}

__device__ __forceinline__ void red_add_v4(float* p, float4 v) {
    asm volatile("red.global.add.v4.f32 [%0], {%1,%2,%3,%4};"
                 :: "l"(p), "f"(v.x), "f"(v.y), "f"(v.z), "f"(v.w) : "memory");
}

// warp computes a 32(m) x 32(n) tile. A fp32 in smem (split per load, 3xTF32);
// B pre-split hi/lo in smem (tf32 bit patterns stored as float).
template<int K, int LDA>
__device__ __forceinline__ void gemm32(const float* __restrict__ sA,
                                       const float* __restrict__ sBh,
                                       const float* __restrict__ sBl,
                                       int mr, int n0, int lane, float acc[2][4][4]) {
    int gid = lane >> 2, tig = lane & 3;
    #pragma unroll
    for (int k0 = 0; k0 < K; k0 += 8) {
        uint32_t ah[2][4], al[2][4];
        #pragma unroll
        for (int f = 0; f < 2; f++) {
            int r0 = mr + f * 16 + gid;
            float a0 = sA[r0 * LDA + k0 + tig];
            float a1 = sA[(r0 + 8) * LDA + k0 + tig];
            float a2 = sA[r0 * LDA + k0 + tig + 4];
            float a3 = sA[(r0 + 8) * LDA + k0 + tig + 4];
            split_tf32(a0, ah[f][0], al[f][0]);
            split_tf32(a1, ah[f][1], al[f][1]);
            split_tf32(a2, ah[f][2], al[f][2]);
            split_tf32(a3, ah[f][3], al[f][3]);
        }
        #pragma unroll
        for (int nt = 0; nt < 4; nt++) {
            int c0 = n0 + nt * 8 + gid;
            uint32_t bh[2], bl[2];
            bh[0] = __float_as_uint(sBh[(k0 + tig) * 72 + c0]);
            bh[1] = __float_as_uint(sBh[(k0 + tig + 4) * 72 + c0]);
            bl[0] = __float_as_uint(sBl[(k0 + tig) * 72 + c0]);
            bl[1] = __float_as_uint(sBl[(k0 + tig + 4) * 72 + c0]);
            #pragma unroll
            for (int f = 0; f < 2; f++) {
                mma_tf32(acc[f][nt], al[f], bh);
                mma_tf32(acc[f][nt], ah[f], bl);
                mma_tf32(acc[f][nt], ah[f], bh);
            }
        }
    }
}

// stage weights once per block: split into hi/lo tf32 smem arrays
__device__ __forceinline__ void stage_split_weights(float* sm,
                                                    const float* __restrict__ w1,
                                                    const float* __restrict__ b1,
                                                    const float* __restrict__ w2,
                                                    const float* __restrict__ b2) {
    int tid = threadIdx.x;
    for (int i = tid; i < 8192; i += 256) {
        uint32_t h, l; split_tf32(w1[i], h, l);
        int k = i >> 6, n = i & 63;
        sm[OFF_B1H + k * 72 + n] = __uint_as_float(h);
        sm[OFF_B1L + k * 72 + n] = __uint_as_float(l);
    }
    for (int i = tid; i < 4096; i += 256) {
        uint32_t h, l; split_tf32(w2[i], h, l);
        int k = i >> 6, n = i & 63;
        sm[OFF_B2H + k * 72 + n] = __uint_as_float(h);
        sm[OFF_B2L + k * 72 + n] = __uint_as_float(l);
    }
    if (tid < 64) { sm[OFF_BI1 + tid] = b1[tid]; sm[OFF_BI2 + tid] = b2[tid]; }
}

__device__ __forceinline__ void epilogue_to_smem(float* dst, const float* bias,
                                                 const float acc[2][4][4],
                                                 int mr, int n0, int gid, int tig) {
    #pragma unroll
    for (int f = 0; f < 2; f++) {
        int r0 = mr + f * 16 + gid;
        #pragma unroll
        for (int nt = 0; nt < 4; nt++) {
            int col = n0 + nt * 8 + 2 * tig;
            float bb0 = bias[col], bb1 = bias[col + 1];
            dst[r0 * 68 + col]           = fmaxf(acc[f][nt][0] + bb0, 0.f);
            dst[r0 * 68 + col + 1]       = fmaxf(acc[f][nt][1] + bb1, 0.f);
            dst[(r0 + 8) * 68 + col]     = fmaxf(acc[f][nt][2] + bb0, 0.f);
            dst[(r0 + 8) * 68 + col + 1] = fmaxf(acc[f][nt][3] + bb1, 0.f);
        }
    }
}

// ---------------- edge index decode ----------------
__global__ void cvt_edges_kernel(const int* __restrict__ raw) {
    __shared__ int is64;
    if (threadIdx.x == 0) {
        int odd = 0;
        #pragma unroll 1
        for (int i = 1; i < 512; i += 2) odd |= raw[i];
        is64 = (odd == 0) ? 1 : 0;
    }
    __syncthreads();
    int e = blockIdx.x * blockDim.x + threadIdx.x;
    if (e < EE) {
        if (is64) { g_src[e] = raw[2 * e];        g_tgt[e] = raw[2 * (EE + e)]; }
        else      { g_src[e] = raw[e];            g_tgt[e] = raw[EE + e]; }
    }
}

// ---------------- encoder ----------------
__global__ void enc_kernel(const float* __restrict__ x,
                           const float* __restrict__ w,
                           const float* __restrict__ b) {
    int tid = blockIdx.x * blockDim.x + threadIdx.x;
    int i = tid >> 6, f = tid & 63;
    float acc = b[f];
    #pragma unroll
    for (int k = 0; k < 4; k++) acc = fmaf(x[i * 4 + k], w[k * 64 + f], acc);
    g_h[tid] = acc;
    g_agg[tid] = 0.f;
}

// ---------------- persistent edge message kernel ----------------
__global__ void __launch_bounds__(256) edge_mma_kernel(const float* __restrict__ w1,
                                                       const float* __restrict__ b1,
                                                       const float* __restrict__ w2,
                                                       const float* __restrict__ b2) {
    extern __shared__ float sm[];
    float* sA = sm + OFF_A;
    float* sM = sm + OFF_M;
    int tid = threadIdx.x;
    stage_split_weights(sm, w1, b1, w2, b2);

    int warp = tid >> 5, lane = tid & 31, gid = lane >> 2, tig = lane & 3;
    int mr = (warp >> 1) * 32, n0 = (warp & 1) * 32;

    for (int tile = blockIdx.x; tile < EE / 128; tile += gridDim.x) {
        int e0 = tile * 128;
        __syncthreads();   // staging done / previous red-loop reads of sA done
        // gather A: 128 edges x 128 feats ([h[tgt] | h[src]])
        #pragma unroll
        for (int it = 0; it < 16; it++) {
            int i = tid + it * 256;
            int e = i >> 5, part = i & 31;
            int node = (part < 16) ? g_tgt[e0 + e] : g_src[e0 + e];
            float4 v = *(const float4*)&g_h[node * 64 + (part & 15) * 4];
            *(float4*)&sA[e * 132 + part * 4] = v;
        }
        __syncthreads();
        float acc[2][4][4] = {};
        gemm32<128, 132>(sA, sm + OFF_B1H, sm + OFF_B1L, mr, n0, lane, acc);
        epilogue_to_smem(sM, sm + OFF_BI1, acc, mr, n0, gid, tig);
        __syncthreads();
        float acc2[2][4][4] = {};
        gemm32<64, 68>(sM, sm + OFF_B2H, sm + OFF_B2L, mr, n0, lane, acc2);
        epilogue_to_smem(sA, sm + OFF_BI2, acc2, mr, n0, gid, tig);  // stage output (stride 68)
        __syncthreads();
        // vectorized scatter-add
        #pragma unroll
        for (int it = 0; it < 8; it++) {
            int idx = tid + it * 256;
            int row = idx >> 4, f4 = idx & 15;
            int t = g_tgt[e0 + row];
            float4 v = *(const float4*)&sA[row * 68 + f4 * 4];
            red_add_v4(&g_agg[t * 64 + f4 * 4], v);
        }
    }
}

// ---------------- persistent node update kernel ----------------
__global__ void __launch_bounds__(256) upd_mma_kernel(const float* __restrict__ w1,
                                                      const float* __restrict__ b1,
                                                      const float* __restrict__ w2,
                                                      const float* __restrict__ b2) {
    extern __shared__ float sm[];
    float* sA = sm + OFF_A;
    float* sM = sm + OFF_M;
    int tid = threadIdx.x;
    // block 0 zeroes the norm stats for the stats kernel that follows
    if (blockIdx.x == 0) {
        for (int i = tid; i < NBATCH * NHID; i += 256) { g_sum[i] = 0.f; g_sqs[i] = 0.f; }
    }
    stage_split_weights(sm, w1, b1, w2, b2);

    int warp = tid >> 5, lane = tid & 31, gid = lane >> 2, tig = lane & 3;
    int mr = (warp >> 1) * 32, n0 = (warp & 1) * 32;

    for (int tile = blockIdx.x; tile < NN / 128; tile += gridDim.x) {
        int nb0 = tile * 128;
        __syncthreads();
        #pragma unroll
        for (int it = 0; it < 16; it++) {
            int i = tid + it * 256;
            int e = i >> 5, part = i & 31;
            int node = nb0 + e;
            float4 v;
            if (part < 16) {
                v = *(const float4*)&g_h[node * 64 + part * 4];
            } else {
                float4* ap = (float4*)&g_agg[node * 64 + (part & 15) * 4];
                v = *ap;
                *ap = make_float4(0.f, 0.f, 0.f, 0.f);
            }
            *(float4*)&sA[e * 132 + part * 4] = v;
        }
        __syncthreads();
        float acc[2][4][4] = {};
        gemm32<128, 132>(sA, sm + OFF_B1H, sm + OFF_B1L, mr, n0, lane, acc);
        epilogue_to_smem(sM, sm + OFF_BI1, acc, mr, n0, gid, tig);
        __syncthreads();
        float acc2[2][4][4] = {};
        gemm32<64, 68>(sM, sm + OFF_B2H, sm + OFF_B2L, mr, n0, lane, acc2);
        epilogue_to_smem(sA, sm + OFF_BI2, acc2, mr, n0, gid, tig);
        __syncthreads();
        #pragma unroll
        for (int it = 0; it < 8; it++) {
            int idx = tid + it * 256;
            int row = idx >> 4, f4 = idx & 15;
            float4 v = *(const float4*)&sA[row * 68 + f4 * 4];
            *(float4*)&g_h[(nb0 + row) * 64 + f4 * 4] = v;
        }
    }
}

// ---------------- instance norm: coalesced stats ----------------
__global__ void norm_stats_kernel() {
    int g = blockIdx.x >> 3, sl = blockIdx.x & 7;      // 64 blocks: 8 graphs x 8 slices
    int tid = threadIdx.x;                              // 256
    int f4 = tid & 15, rc = tid >> 4;                   // 16 f4-cols x 16 row-chunks
    int row0 = g * NSAMPLES + sl * 256 + rc * 16;
    float4 s = make_float4(0.f, 0.f, 0.f, 0.f);
    float4 q = make_float4(0.f, 0.f, 0.f, 0.f);
    #pragma unroll
    for (int r = 0; r < 16; r++) {
        float4 v = *(const float4*)&g_h[(row0 + r) * 64 + f4 * 4];
        s.x += v.x; s.y += v.y; s.z += v.z; s.w += v.w;
        q.x = fmaf(v.x, v.x, q.x); q.y = fmaf(v.y, v.y, q.y);
        q.z = fmaf(v.z, v.z, q.z); q.w = fmaf(v.w, v.w, q.w);
    }
    __shared__ float ssum[16][64], ssq[16][64];
    *(float4*)&ssum[rc][f4 * 4] = s;
    *(float4*)&ssq[rc][f4 * 4]  = q;
    __syncthreads();
    if (tid < 64) {
        float ts = 0.f, tq = 0.f;
        #pragma unroll
        for (int r = 0; r < 16; r++) { ts += ssum[r][tid]; tq += ssq[r][tid]; }
        atomicAdd(&g_sum[g * 64 + tid], ts);
        atomicAdd(&g_sqs[g * 64 + tid], tq);
    }
}

// ---------------- instance norm: coalesced apply ----------------
__global__ void norm_apply_kernel() {
    int g = blockIdx.x >> 3, sl = blockIdx.x & 7;
    int tid = threadIdx.x;
    __shared__ float smean[64], srstd[64];
    if (tid < 64) {
        float mean = g_sum[g * 64 + tid] * (1.f / NSAMPLES);
        float var  = g_sqs[g * 64 + tid] * (1.f / NSAMPLES) - mean * mean;
        smean[tid] = mean;
        srstd[tid] = rsqrtf(var + EPSI);
    }
    __syncthreads();
    int f4 = tid & 15, rc = tid >> 4;
    int row0 = g * NSAMPLES + sl * 256 + rc * 16;
    float4 mn = *(const float4*)&smean[f4 * 4];
    float4 rs = *(const float4*)&srstd[f4 * 4];
    #pragma unroll
    for (int r = 0; r < 16; r++) {
        float4* p = (float4*)&g_h[(row0 + r) * 64 + f4 * 4];
        float4 v = *p;
        v.x = (v.x - mn.x) * rs.x; v.y = (v.y - mn.y) * rs.y;
        v.z = (v.z - mn.z) * rs.z; v.w = (v.w - mn.w) * rs.w;
        *p = v;
    }
}

__global__ void zero_small_kernel() {
    int t = threadIdx.x;
    if (t < NBATCH) { g_t2[t] = 0.f; g_t3[t] = 0.f; }
}

// ---------------- decoder + t2 term ----------------
__global__ void dec_kernel(const float* __restrict__ w, const float* __restrict__ b) {
    int i = blockIdx.x * blockDim.x + threadIdx.x;
    const float* hr = &g_h[i * 64];
    float a0 = b[0], a1 = b[1], a2 = b[2], a3 = b[3];
    #pragma unroll 8
    for (int k = 0; k < 64; k++) {
        float hv = hr[k];
        a0 = fmaf(hv, w[k * 4 + 0], a0);
        a1 = fmaf(hv, w[k * 4 + 1], a1);
        a2 = fmaf(hv, w[k * 4 + 2], a2);
        a3 = fmaf(hv, w[k * 4 + 3], a3);
    }
    a0 = 1.f / (1.f + expf(-a0));
    a1 = 1.f / (1.f + expf(-a1));
    a2 = 1.f / (1.f + expf(-a2));
    a3 = 1.f / (1.f + expf(-a3));
    g_X[i * 4 + 0] = a0; g_X[i * 4 + 1] = a1;
    g_X[i * 4 + 2] = a2; g_X[i * 4 + 3] = a3;
    float pr = (1.f - a0 * a0) * (1.f - a1 * a1) * (1.f - a2 * a2) * (1.f - a3 * a3);
    #pragma unroll
    for (int off = 16; off > 0; off >>= 1)
        pr += __shfl_down_sync(0xffffffffu, pr, off);
    if ((threadIdx.x & 31) == 0) atomicAdd(&g_t2[i >> 11], pr);
}

// ---------------- t3 pairwise term ----------------
__global__ void t3_kernel() {
    int b = blockIdx.x;
    int g = b >> 6, ic = (b >> 2) & 15, jc = b & 3;
    int tid = threadIdx.x;         // 128
    __shared__ float4 sX[512];
    const float4* Xg = (const float4*)&g_X[(g * NSAMPLES) * 4];
    for (int j = tid; j < 512; j += 128) sX[j] = Xg[jc * 512 + j];
    __syncthreads();
    float4 xi = Xg[ic * 128 + tid];
    float acc = 0.f;
    #pragma unroll 4
    for (int j = 0; j < 512; j++) {
        float4 xj = sX[j];
        float p = (1.f - fmaxf(xi.x, xj.x)) * (1.f - fmaxf(xi.y, xj.y)) *
                  (1.f - fmaxf(xi.z, xj.z)) * (1.f - fmaxf(xi.w, xj.w));
        acc += p;
    }
    __shared__ float red[128];
    red[tid] = acc; __syncthreads();
    for (int off = 64; off > 0; off >>= 1) {
        if (tid < off) red[tid] += red[tid + off];
        __syncthreads();
    }
    if (tid == 0) atomicAdd(&g_t3[g], red[0]);
}

// ---------------- emit ----------------
__global__ void emit_kernel(float* __restrict__ out, int out_size) {
    int tid = blockIdx.x * blockDim.x + threadIdx.x;
    float loss = 0.f;
    if (tid == 0) {
        const float t1 = 1.0f / 81.0f;
        #pragma unroll
        for (int g = 0; g < NBATCH; g++) {
            float l = t1 - g_t2[g] * (2.0f / 32768.0f)
                         + g_t3[g] * (1.0f / (2048.f * 2048.f));
            loss += l;
        }
        loss *= (1.0f / NBATCH);
    }
    if (out_size == NN * DIMX) {
        if (tid < NN * DIMX) out[tid] = g_X[tid];
    } else {
        if (tid == 0) out[0] = loss;
        int idx = tid - 1;
        if (idx >= 0 && idx < NN * DIMX && (idx + 1) < out_size) out[1 + idx] = g_X[idx];
    }
}

// ---------------- launch ----------------
extern "C" void kernel_launch(void* const* d_in, const int* in_sizes, int n_in,
                              void* d_out, int out_size) {
    const float* x     = (const float*)d_in[0];
    const int*   eiraw = (const int*)  d_in[1];
    const float* enc_w = (const float*)d_in[2];
    const float* enc_b = (const float*)d_in[3];
    const float* m1_w  = (const float*)d_in[4];
    const float* m1_b  = (const float*)d_in[5];
    const float* m2_w  = (const float*)d_in[6];
    const float* m2_b  = (const float*)d_in[7];
    const float* u1_w  = (const float*)d_in[8];
    const float* u1_b  = (const float*)d_in[9];
    const float* u2_w  = (const float*)d_in[10];
    const float* u2_b  = (const float*)d_in[11];
    const float* dec_w = (const float*)d_in[12];
    const float* dec_b = (const float*)d_in[13];
    float* out = (float*)d_out;

    (void)cudaFuncSetAttribute(edge_mma_kernel, cudaFuncAttributeMaxDynamicSharedMemorySize, SMEM_MMA_BYTES);
    (void)cudaFuncSetAttribute(upd_mma_kernel,  cudaFuncAttributeMaxDynamicSharedMemorySize, SMEM_MMA_BYTES);

    cvt_edges_kernel<<<(EE + 255) / 256, 256>>>(eiraw);
    enc_kernel<<<NN * NHID / 256, 256>>>(x, enc_w, enc_b);
    for (int l = 0; l < NLAYERS; l++) {
        edge_mma_kernel<<<148, 256, SMEM_MMA_BYTES>>>(
            m1_w + l * 128 * 64, m1_b + l * 64, m2_w + l * 64 * 64, m2_b + l * 64);
        upd_mma_kernel<<<64, 256, SMEM_MMA_BYTES>>>(
            u1_w + l * 128 * 64, u1_b + l * 64, u2_w + l * 64 * 64, u2_b + l * 64);
        norm_stats_kernel<<<64, 256>>>();
        norm_apply_kernel<<<64, 256>>>();
    }
    zero_small_kernel<<<1, 32>>>();
    dec_kernel<<<NN / 256, 256>>>(dec_w, dec_b);
    t3_kernel<<<512, 128>>>();
    emit_kernel<<<(NN * DIMX + 1 + 255) / 256, 256>>>(out, out_size);
}

// round 11
// speedup vs baseline: 2.3616x; 1.2380x over previous
#include <cuda_runtime.h>
#include <math.h>
#include <stdint.h>

#define NBATCH   8
#define NSAMPLES 2048
#define DIMX     4
#define NHID     64
#define NLAYERS  3
#define NN       (NBATCH * NSAMPLES)     // 16384 nodes
#define EE       (NN * 16)               // 262144 edges
#define EPSI     1e-5f

// ---------------- static device scratch ----------------
__device__ float g_h[NN * NHID];
__device__ float g_agg[NN * NHID];
__device__ __align__(16) float g_PQ[NN * 128];   // [P|Q] per node (P includes b1)
__device__ __align__(16) float g_X[NN * DIMX];
__device__ int   g_src[EE];
__device__ int   g_tgt[EE];
__device__ float g_t2[NBATCH];
__device__ float g_t3[NBATCH];
__device__ float g_sum[NBATCH * NHID];
__device__ float g_sqs[NBATCH * NHID];

// ---------------- tf32 helpers ----------------
__device__ __forceinline__ void split_tf32(float x, uint32_t& hi, uint32_t& lo) {
    uint32_t h;
    asm("cvt.rna.tf32.f32 %0, %1;" : "=r"(h) : "f"(x));
    float l = x - __uint_as_float(h);
    uint32_t lr;
    asm("cvt.rna.tf32.f32 %0, %1;" : "=r"(lr) : "f"(l));
    hi = h; lo = lr;
}

__device__ __forceinline__ void mma_tf32(float c[4], const uint32_t a[4], const uint32_t b[2]) {
    asm volatile(
        "mma.sync.aligned.m16n8k8.row.col.f32.tf32.tf32.f32 "
        "{%0,%1,%2,%3}, {%4,%5,%6,%7}, {%8,%9}, {%0,%1,%2,%3};"
        : "+f"(c[0]), "+f"(c[1]), "+f"(c[2]), "+f"(c[3])
        : "r"(a[0]), "r"(a[1]), "r"(a[2]), "r"(a[3]), "r"(b[0]), "r"(b[1]));
}

__device__ __forceinline__ void red_add_v4(float* p, float4 v) {
    asm volatile("red.global.add.v4.f32 [%0], {%1,%2,%3,%4};"
                 :: "l"(p), "f"(v.x), "f"(v.y), "f"(v.z), "f"(v.w) : "memory");
}

// warp computes a 32(m) x (NT*8)(n) tile; A fp32 in smem (3xTF32 split at load),
// B pre-split hi/lo tf32 bit-patterns in smem.
template<int K, int LDA, int NT, int LDB>
__device__ __forceinline__ void gemm_mt(const float* __restrict__ sA,
                                        const float* __restrict__ sBh,
                                        const float* __restrict__ sBl,
                                        int mr, int n0, int lane, float acc[2][NT][4]) {
    int gid = lane >> 2, tig = lane & 3;
    #pragma unroll
    for (int k0 = 0; k0 < K; k0 += 8) {
        uint32_t ah[2][4], al[2][4];
        #pragma unroll
        for (int f = 0; f < 2; f++) {
            int r0 = mr + f * 16 + gid;
            split_tf32(sA[r0 * LDA + k0 + tig],           ah[f][0], al[f][0]);
            split_tf32(sA[(r0 + 8) * LDA + k0 + tig],     ah[f][1], al[f][1]);
            split_tf32(sA[r0 * LDA + k0 + tig + 4],       ah[f][2], al[f][2]);
            split_tf32(sA[(r0 + 8) * LDA + k0 + tig + 4], ah[f][3], al[f][3]);
        }
        #pragma unroll
        for (int nt = 0; nt < NT; nt++) {
            int c0 = n0 + nt * 8 + gid;
            uint32_t bh[2], bl[2];
            bh[0] = __float_as_uint(sBh[(k0 + tig) * LDB + c0]);
            bh[1] = __float_as_uint(sBh[(k0 + tig + 4) * LDB + c0]);
            bl[0] = __float_as_uint(sBl[(k0 + tig) * LDB + c0]);
            bl[1] = __float_as_uint(sBl[(k0 + tig + 4) * LDB + c0]);
            #pragma unroll
            for (int f = 0; f < 2; f++) {
                mma_tf32(acc[f][nt], al[f], bh);
                mma_tf32(acc[f][nt], ah[f], bl);
                mma_tf32(acc[f][nt], ah[f], bh);
            }
        }
    }
}

// ---------------- edge index decode ----------------
__global__ void cvt_edges_kernel(const int* __restrict__ raw) {
    __shared__ int is64;
    if (threadIdx.x == 0) {
        int odd = 0;
        #pragma unroll 1
        for (int i = 1; i < 512; i += 2) odd |= raw[i];
        is64 = (odd == 0) ? 1 : 0;
    }
    __syncthreads();
    int e = blockIdx.x * blockDim.x + threadIdx.x;
    if (e < EE) {
        if (is64) { g_src[e] = raw[2 * e];        g_tgt[e] = raw[2 * (EE + e)]; }
        else      { g_src[e] = raw[e];            g_tgt[e] = raw[EE + e]; }
    }
}

// ---------------- encoder ----------------
__global__ void enc_kernel(const float* __restrict__ x,
                           const float* __restrict__ w,
                           const float* __restrict__ b) {
    int tid = blockIdx.x * blockDim.x + threadIdx.x;
    int i = tid >> 6, f = tid & 63;
    float acc = b[f];
    #pragma unroll
    for (int k = 0; k < 4; k++) acc = fmaf(x[i * 4 + k], w[k * 64 + f], acc);
    g_h[tid] = acc;
    g_agg[tid] = 0.f;
}

// ================= PQ kernel: [P|Q] = h @ [W1a ; W1b]  (P gets +b1) =================
// smem: sA 128x68 = 8704 ; Bh 64x136 = 8704 ; Bl 8704   -> 104448 B, 2 blocks/SM
#define PQ_A   0
#define PQ_BH  8704
#define PQ_BL  17408
#define PQ_FLOATS 26112
#define PQ_BYTES  (PQ_FLOATS * 4)

__global__ void __launch_bounds__(256) pq_kernel(const float* __restrict__ w1,
                                                 const float* __restrict__ b1) {
    extern __shared__ float sm[];
    float* sA  = sm + PQ_A;
    float* sBh = sm + PQ_BH;
    float* sBl = sm + PQ_BL;
    int tid = threadIdx.x;
    int nb0 = blockIdx.x * 128;

    // stage B' = 64(k) x 128(n): n<64 -> W1a[k][n]=w1[k*64+n]; n>=64 -> W1b=w1[(64+k)*64+n-64]
    for (int i = tid; i < 8192; i += 256) {
        int k = i >> 7, n = i & 127;
        float w = w1[((n < 64) ? k : (64 + k)) * 64 + (n & 63)];
        uint32_t h, l; split_tf32(w, h, l);
        sBh[k * 136 + n] = __uint_as_float(h);
        sBl[k * 136 + n] = __uint_as_float(l);
    }
    // load h tile (dense)
    #pragma unroll
    for (int it = 0; it < 8; it++) {
        int idx = tid + it * 256;
        int row = idx >> 4, f4 = idx & 15;
        float4 v = *(const float4*)&g_h[(nb0 + row) * 64 + f4 * 4];
        *(float4*)&sA[row * 68 + f4 * 4] = v;
    }
    __syncthreads();

    int warp = tid >> 5, lane = tid & 31, gid = lane >> 2, tig = lane & 3;
    int mr = (warp >> 1) * 32, n0 = (warp & 1) * 64;

    float acc[2][8][4] = {};
    gemm_mt<64, 68, 8, 136>(sA, sBh, sBl, mr, n0, lane, acc);

    #pragma unroll
    for (int f = 0; f < 2; f++) {
        int r0 = mr + f * 16 + gid;
        #pragma unroll
        for (int nt = 0; nt < 8; nt++) {
            int col = n0 + nt * 8 + 2 * tig;
            float bb0 = (col < 64) ? __ldg(b1 + col)     : 0.f;
            float bb1 = (col < 64) ? __ldg(b1 + col + 1) : 0.f;
            g_PQ[(nb0 + r0) * 128 + col]         = acc[f][nt][0] + bb0;
            g_PQ[(nb0 + r0) * 128 + col + 1]     = acc[f][nt][1] + bb1;
            g_PQ[(nb0 + r0 + 8) * 128 + col]     = acc[f][nt][2] + bb0;
            g_PQ[(nb0 + r0 + 8) * 128 + col + 1] = acc[f][nt][3] + bb1;
        }
    }
}

// ================= edge kernel: m=relu(P[tgt]+Q[src]); out=relu(m@W2+b2); scatter =================
// smem: sM 128x68, sO 128x68, B2h/B2l 64x72, b2  -> 106752 B, 2 blocks/SM
#define ESM_M    0
#define ESM_O    8704
#define ESM_B2H  17408
#define ESM_B2L  22016
#define ESM_BI2  26624
#define ESM_FLOATS 26688
#define ESM_BYTES  (ESM_FLOATS * 4)

__global__ void __launch_bounds__(256) edge_mma_kernel(const float* __restrict__ w2,
                                                       const float* __restrict__ b2) {
    extern __shared__ float sm[];
    float* sM = sm + ESM_M;
    float* sO = sm + ESM_O;
    int tid = threadIdx.x;

    // block 0 zeroes norm stats for the upd kernel that follows
    if (blockIdx.x == 0) {
        for (int i = tid; i < NBATCH * NHID; i += 256) { g_sum[i] = 0.f; g_sqs[i] = 0.f; }
    }
    for (int i = tid; i < 4096; i += 256) {
        uint32_t h, l; split_tf32(w2[i], h, l);
        int k = i >> 6, n = i & 63;
        sm[ESM_B2H + k * 72 + n] = __uint_as_float(h);
        sm[ESM_B2L + k * 72 + n] = __uint_as_float(l);
    }
    if (tid < 64) sm[ESM_BI2 + tid] = b2[tid];

    int warp = tid >> 5, lane = tid & 31, gid = lane >> 2, tig = lane & 3;
    int mr = (warp >> 1) * 32, n0 = (warp & 1) * 32;

    for (int tile = blockIdx.x; tile < EE / 128; tile += gridDim.x) {
        int e0 = tile * 128;
        // gather + add + relu -> sM
        #pragma unroll
        for (int it = 0; it < 8; it++) {
            int idx = tid + it * 256;
            int row = idx >> 4, f4 = idx & 15;
            int t = g_tgt[e0 + row], s = g_src[e0 + row];
            float4 p = *(const float4*)&g_PQ[t * 128 + f4 * 4];
            float4 q = *(const float4*)&g_PQ[s * 128 + 64 + f4 * 4];
            float4 v;
            v.x = fmaxf(p.x + q.x, 0.f); v.y = fmaxf(p.y + q.y, 0.f);
            v.z = fmaxf(p.z + q.z, 0.f); v.w = fmaxf(p.w + q.w, 0.f);
            *(float4*)&sM[row * 68 + f4 * 4] = v;
        }
        __syncthreads();
        float acc[2][4][4] = {};
        gemm_mt<64, 68, 4, 72>(sM, sm + ESM_B2H, sm + ESM_B2L, mr, n0, lane, acc);
        #pragma unroll
        for (int f = 0; f < 2; f++) {
            int r0 = mr + f * 16 + gid;
            #pragma unroll
            for (int nt = 0; nt < 4; nt++) {
                int col = n0 + nt * 8 + 2 * tig;
                float bb0 = sm[ESM_BI2 + col], bb1 = sm[ESM_BI2 + col + 1];
                sO[r0 * 68 + col]           = fmaxf(acc[f][nt][0] + bb0, 0.f);
                sO[r0 * 68 + col + 1]       = fmaxf(acc[f][nt][1] + bb1, 0.f);
                sO[(r0 + 8) * 68 + col]     = fmaxf(acc[f][nt][2] + bb0, 0.f);
                sO[(r0 + 8) * 68 + col + 1] = fmaxf(acc[f][nt][3] + bb1, 0.f);
            }
        }
        __syncthreads();
        #pragma unroll
        for (int it = 0; it < 8; it++) {
            int idx = tid + it * 256;
            int row = idx >> 4, f4 = idx & 15;
            int t = g_tgt[e0 + row];
            float4 v = *(const float4*)&sO[row * 68 + f4 * 4];
            red_add_v4(&g_agg[t * 64 + f4 * 4], v);
        }
    }
}

// ================= node update kernel (K=128 GEMM1, K=64 GEMM2) + fused norm stats =================
#define OFF_A    0
#define OFF_M    16896
#define OFF_B1H  25600
#define OFF_B1L  34816
#define OFF_B2H  44032
#define OFF_B2L  48640
#define OFF_BI1  53248
#define OFF_BI2  53312
#define SMEM_MMA_FLOATS 53376
#define SMEM_MMA_BYTES  (SMEM_MMA_FLOATS * 4)

__global__ void __launch_bounds__(256) upd_mma_kernel(const float* __restrict__ w1,
                                                      const float* __restrict__ b1,
                                                      const float* __restrict__ w2,
                                                      const float* __restrict__ b2) {
    extern __shared__ float sm[];
    float* sA = sm + OFF_A;
    float* sM = sm + OFF_M;
    int tid = threadIdx.x;
    for (int i = tid; i < 8192; i += 256) {
        uint32_t h, l; split_tf32(w1[i], h, l);
        int k = i >> 6, n = i & 63;
        sm[OFF_B1H + k * 72 + n] = __uint_as_float(h);
        sm[OFF_B1L + k * 72 + n] = __uint_as_float(l);
    }
    for (int i = tid; i < 4096; i += 256) {
        uint32_t h, l; split_tf32(w2[i], h, l);
        int k = i >> 6, n = i & 63;
        sm[OFF_B2H + k * 72 + n] = __uint_as_float(h);
        sm[OFF_B2L + k * 72 + n] = __uint_as_float(l);
    }
    if (tid < 64) { sm[OFF_BI1 + tid] = b1[tid]; sm[OFF_BI2 + tid] = b2[tid]; }

    int warp = tid >> 5, lane = tid & 31, gid = lane >> 2, tig = lane & 3;
    int mr = (warp >> 1) * 32, n0 = (warp & 1) * 32;
    int nb0 = blockIdx.x * 128;

    #pragma unroll
    for (int it = 0; it < 16; it++) {
        int i = tid + it * 256;
        int e = i >> 5, part = i & 31;
        int node = nb0 + e;
        float4 v;
        if (part < 16) {
            v = *(const float4*)&g_h[node * 64 + part * 4];
        } else {
            float4* ap = (float4*)&g_agg[node * 64 + (part & 15) * 4];
            v = *ap;
            *ap = make_float4(0.f, 0.f, 0.f, 0.f);
        }
        *(float4*)&sA[e * 132 + part * 4] = v;
    }
    __syncthreads();
    float acc[2][4][4] = {};
    gemm_mt<128, 132, 4, 72>(sA, sm + OFF_B1H, sm + OFF_B1L, mr, n0, lane, acc);
    #pragma unroll
    for (int f = 0; f < 2; f++) {
        int r0 = mr + f * 16 + gid;
        #pragma unroll
        for (int nt = 0; nt < 4; nt++) {
            int col = n0 + nt * 8 + 2 * tig;
            float bb0 = sm[OFF_BI1 + col], bb1 = sm[OFF_BI1 + col + 1];
            sM[r0 * 68 + col]           = fmaxf(acc[f][nt][0] + bb0, 0.f);
            sM[r0 * 68 + col + 1]       = fmaxf(acc[f][nt][1] + bb1, 0.f);
            sM[(r0 + 8) * 68 + col]     = fmaxf(acc[f][nt][2] + bb0, 0.f);
            sM[(r0 + 8) * 68 + col + 1] = fmaxf(acc[f][nt][3] + bb1, 0.f);
        }
    }
    __syncthreads();
    float acc2[2][4][4] = {};
    gemm_mt<64, 68, 4, 72>(sM, sm + OFF_B2H, sm + OFF_B2L, mr, n0, lane, acc2);
    #pragma unroll
    for (int f = 0; f < 2; f++) {
        int r0 = mr + f * 16 + gid;
        #pragma unroll
        for (int nt = 0; nt < 4; nt++) {
            int col = n0 + nt * 8 + 2 * tig;
            float bb0 = sm[OFF_BI2 + col], bb1 = sm[OFF_BI2 + col + 1];
            sA[r0 * 68 + col]           = fmaxf(acc2[f][nt][0] + bb0, 0.f);
            sA[r0 * 68 + col + 1]       = fmaxf(acc2[f][nt][1] + bb1, 0.f);
            sA[(r0 + 8) * 68 + col]     = fmaxf(acc2[f][nt][2] + bb0, 0.f);
            sA[(r0 + 8) * 68 + col + 1] = fmaxf(acc2[f][nt][3] + bb1, 0.f);
        }
    }
    __syncthreads();
    // store + fused per-feature stats (tile is within one graph: 2048 % 128 == 0)
    int f4 = tid & 15;
    float4 s = make_float4(0.f, 0.f, 0.f, 0.f);
    float4 q = make_float4(0.f, 0.f, 0.f, 0.f);
    #pragma unroll
    for (int it = 0; it < 8; it++) {
        int idx = tid + it * 256;
        int row = idx >> 4;
        float4 v = *(const float4*)&sA[row * 68 + f4 * 4];
        *(float4*)&g_h[(nb0 + row) * 64 + f4 * 4] = v;
        s.x += v.x; s.y += v.y; s.z += v.z; s.w += v.w;
        q.x = fmaf(v.x, v.x, q.x); q.y = fmaf(v.y, v.y, q.y);
        q.z = fmaf(v.z, v.z, q.z); q.w = fmaf(v.w, v.w, q.w);
    }
    int g = nb0 >> 11;
    red_add_v4(&g_sum[g * 64 + f4 * 4], s);
    red_add_v4(&g_sqs[g * 64 + f4 * 4], q);
}

// ---------------- instance norm: coalesced apply ----------------
__global__ void norm_apply_kernel() {
    int g = blockIdx.x >> 3, sl = blockIdx.x & 7;
    int tid = threadIdx.x;
    __shared__ float smean[64], srstd[64];
    if (tid < 64) {
        float mean = g_sum[g * 64 + tid] * (1.f / NSAMPLES);
        float var  = g_sqs[g * 64 + tid] * (1.f / NSAMPLES) - mean * mean;
        smean[tid] = mean;
        srstd[tid] = rsqrtf(var + EPSI);
    }
    __syncthreads();
    int f4 = tid & 15, rc = tid >> 4;
    int row0 = g * NSAMPLES + sl * 256 + rc * 16;
    float4 mn = *(const float4*)&smean[f4 * 4];
    float4 rs = *(const float4*)&srstd[f4 * 4];
    #pragma unroll
    for (int r = 0; r < 16; r++) {
        float4* p = (float4*)&g_h[(row0 + r) * 64 + f4 * 4];
        float4 v = *p;
        v.x = (v.x - mn.x) * rs.x; v.y = (v.y - mn.y) * rs.y;
        v.z = (v.z - mn.z) * rs.z; v.w = (v.w - mn.w) * rs.w;
        *p = v;
    }
}

__global__ void zero_small_kernel() {
    int t = threadIdx.x;
    if (t < NBATCH) { g_t2[t] = 0.f; g_t3[t] = 0.f; }
}

// ---------------- decoder + t2 term ----------------
__global__ void dec_kernel(const float* __restrict__ w, const float* __restrict__ b) {
    int i = blockIdx.x * blockDim.x + threadIdx.x;
    const float* hr = &g_h[i * 64];
    float a0 = b[0], a1 = b[1], a2 = b[2], a3 = b[3];
    #pragma unroll 8
    for (int k = 0; k < 64; k++) {
        float hv = hr[k];
        a0 = fmaf(hv, w[k * 4 + 0], a0);
        a1 = fmaf(hv, w[k * 4 + 1], a1);
        a2 = fmaf(hv, w[k * 4 + 2], a2);
        a3 = fmaf(hv, w[k * 4 + 3], a3);
    }
    a0 = 1.f / (1.f + expf(-a0));
    a1 = 1.f / (1.f + expf(-a1));
    a2 = 1.f / (1.f + expf(-a2));
    a3 = 1.f / (1.f + expf(-a3));
    g_X[i * 4 + 0] = a0; g_X[i * 4 + 1] = a1;
    g_X[i * 4 + 2] = a2; g_X[i * 4 + 3] = a3;
    float pr = (1.f - a0 * a0) * (1.f - a1 * a1) * (1.f - a2 * a2) * (1.f - a3 * a3);
    #pragma unroll
    for (int off = 16; off > 0; off >>= 1)
        pr += __shfl_down_sync(0xffffffffu, pr, off);
    if ((threadIdx.x & 31) == 0) atomicAdd(&g_t2[i >> 11], pr);
}

// ---------------- t3 pairwise term ----------------
__global__ void t3_kernel() {
    int b = blockIdx.x;
    int g = b >> 6, ic = (b >> 2) & 15, jc = b & 3;
    int tid = threadIdx.x;         // 128
    __shared__ float4 sX[512];
    const float4* Xg = (const float4*)&g_X[(g * NSAMPLES) * 4];
    for (int j = tid; j < 512; j += 128) sX[j] = Xg[jc * 512 + j];
    __syncthreads();
    float4 xi = Xg[ic * 128 + tid];
    float acc = 0.f;
    #pragma unroll 4
    for (int j = 0; j < 512; j++) {
        float4 xj = sX[j];
        float p = (1.f - fmaxf(xi.x, xj.x)) * (1.f - fmaxf(xi.y, xj.y)) *
                  (1.f - fmaxf(xi.z, xj.z)) * (1.f - fmaxf(xi.w, xj.w));
        acc += p;
    }
    __shared__ float red[128];
    red[tid] = acc; __syncthreads();
    for (int off = 64; off > 0; off >>= 1) {
        if (tid < off) red[tid] += red[tid + off];
        __syncthreads();
    }
    if (tid == 0) atomicAdd(&g_t3[g], red[0]);
}

// ---------------- emit ----------------
__global__ void emit_kernel(float* __restrict__ out, int out_size) {
    int tid = blockIdx.x * blockDim.x + threadIdx.x;
    float loss = 0.f;
    if (tid == 0) {
        const float t1 = 1.0f / 81.0f;
        #pragma unroll
        for (int g = 0; g < NBATCH; g++) {
            float l = t1 - g_t2[g] * (2.0f / 32768.0f)
                         + g_t3[g] * (1.0f / (2048.f * 2048.f));
            loss += l;
        }
        loss *= (1.0f / NBATCH);
    }
    if (out_size == NN * DIMX) {
        if (tid < NN * DIMX) out[tid] = g_X[tid];
    } else {
        if (tid == 0) out[0] = loss;
        int idx = tid - 1;
        if (idx >= 0 && idx < NN * DIMX && (idx + 1) < out_size) out[1 + idx] = g_X[idx];
    }
}

// ---------------- launch ----------------
extern "C" void kernel_launch(void* const* d_in, const int* in_sizes, int n_in,
                              void* d_out, int out_size) {
    const float* x     = (const float*)d_in[0];
    const int*   eiraw = (const int*)  d_in[1];
    const float* enc_w = (const float*)d_in[2];
    const float* enc_b = (const float*)d_in[3];
    const float* m1_w  = (const float*)d_in[4];
    const float* m1_b  = (const float*)d_in[5];
    const float* m2_w  = (const float*)d_in[6];
    const float* m2_b  = (const float*)d_in[7];
    const float* u1_w  = (const float*)d_in[8];
    const float* u1_b  = (const float*)d_in[9];
    const float* u2_w  = (const float*)d_in[10];
    const float* u2_b  = (const float*)d_in[11];
    const float* dec_w = (const float*)d_in[12];
    const float* dec_b = (const float*)d_in[13];
    float* out = (float*)d_out;

    (void)cudaFuncSetAttribute(pq_kernel,       cudaFuncAttributeMaxDynamicSharedMemorySize, PQ_BYTES);
    (void)cudaFuncSetAttribute(edge_mma_kernel, cudaFuncAttributeMaxDynamicSharedMemorySize, ESM_BYTES);
    (void)cudaFuncSetAttribute(upd_mma_kernel,  cudaFuncAttributeMaxDynamicSharedMemorySize, SMEM_MMA_BYTES);

    cvt_edges_kernel<<<(EE + 255) / 256, 256>>>(eiraw);
    enc_kernel<<<NN * NHID / 256, 256>>>(x, enc_w, enc_b);
    for (int l = 0; l < NLAYERS; l++) {
        pq_kernel<<<NN / 128, 256, PQ_BYTES>>>(m1_w + l * 128 * 64, m1_b + l * 64);
        edge_mma_kernel<<<296, 256, ESM_BYTES>>>(m2_w + l * 64 * 64, m2_b + l * 64);
        upd_mma_kernel<<<NN / 128, 256, SMEM_MMA_BYTES>>>(
            u1_w + l * 128 * 64, u1_b + l * 64, u2_w + l * 64 * 64, u2_b + l * 64);
        norm_apply_kernel<<<64, 256>>>();
    }
    zero_small_kernel<<<1, 32>>>();
    dec_kernel<<<NN / 256, 256>>>(dec_w, dec_b);
    t3_kernel<<<512, 128>>>();
    emit_kernel<<<(NN * DIMX + 1 + 255) / 256, 256>>>(out, out_size);
}

// round 13
// speedup vs baseline: 3.1185x; 1.3205x over previous
#include <cuda_runtime.h>
#include <math.h>
#include <stdint.h>

#define NBATCH   8
#define NSAMPLES 2048
#define DIMX     4
#define NHID     64
#define NLAYERS  3
#define NN       (NBATCH * NSAMPLES)     // 16384 nodes
#define EE       (NN * 16)               // 262144 edges
#define EPSI     1e-5f

// ---------------- static device scratch ----------------
__device__ float g_h[NN * NHID];
__device__ float g_agg[NN * NHID];
__device__ __align__(16) float g_PQ[NN * 128];   // [P|Q] per node (P includes b1)
__device__ __align__(16) float g_X[NN * DIMX];
__device__ int   g_src[EE];
__device__ int   g_tgt[EE];
__device__ float g_t2[NBATCH];
__device__ float g_t3[NBATCH];
__device__ float g_sum[NBATCH * NHID];
__device__ float g_sqs[NBATCH * NHID];

// ---------------- tf32 helpers ----------------
__device__ __forceinline__ void split_tf32(float x, uint32_t& hi, uint32_t& lo) {
    uint32_t h;
    asm("cvt.rna.tf32.f32 %0, %1;" : "=r"(h) : "f"(x));
    float l = x - __uint_as_float(h);
    uint32_t lr;
    asm("cvt.rna.tf32.f32 %0, %1;" : "=r"(lr) : "f"(l));
    hi = h; lo = lr;
}

__device__ __forceinline__ void mma_tf32(float c[4], const uint32_t a[4], const uint32_t b[2]) {
    asm volatile(
        "mma.sync.aligned.m16n8k8.row.col.f32.tf32.tf32.f32 "
        "{%0,%1,%2,%3}, {%4,%5,%6,%7}, {%8,%9}, {%0,%1,%2,%3};"
        : "+f"(c[0]), "+f"(c[1]), "+f"(c[2]), "+f"(c[3])
        : "r"(a[0]), "r"(a[1]), "r"(a[2]), "r"(a[3]), "r"(b[0]), "r"(b[1]));
}

__device__ __forceinline__ void red_add_v4(float* p, float4 v) {
    asm volatile("red.global.add.v4.f32 [%0], {%1,%2,%3,%4};"
                 :: "l"(p), "f"(v.x), "f"(v.y), "f"(v.z), "f"(v.w) : "memory");
}

// ---------------- paired-transposed B staging ----------------
// w: [K][64] row-major (k-major in gmem). dst arrays: [64 n][LDB] with k-pair permute:
// within each 8-k block, slot = 2*(k&3) + (k>>2&1), so (k+tig, k+tig+4) is a float2 at k0+2*tig.
template<int K, int LDB>
__device__ __forceinline__ void stage_Bt(float* dh, float* dl, const float* __restrict__ w) {
    int tid = threadIdx.x;
    for (int i = tid; i < K * 64; i += 256) {
        int k = i >> 6, n = i & 63;
        uint32_t h, l; split_tf32(w[i], h, l);
        int pos = n * LDB + (k & ~7) + ((k & 3) << 1) + ((k >> 2) & 1);
        dh[pos] = __uint_as_float(h);
        dl[pos] = __uint_as_float(l);
    }
}

// ---------------- GEMM: A fp32 (split in loop), B paired-transposed hi/lo ----------------
template<int K, int LDA, int NT, int LDB>
__device__ __forceinline__ void gemm_sp(const float* __restrict__ sA,
                                        const float* __restrict__ sBh,
                                        const float* __restrict__ sBl,
                                        int mr, int n0, int lane, float acc[2][NT][4]) {
    int gid = lane >> 2, tig = lane & 3;
    #pragma unroll
    for (int k0 = 0; k0 < K; k0 += 8) {
        uint32_t ah[2][4], al[2][4];
        #pragma unroll
        for (int f = 0; f < 2; f++) {
            int r0 = mr + f * 16 + gid;
            split_tf32(sA[r0 * LDA + k0 + tig],           ah[f][0], al[f][0]);
            split_tf32(sA[(r0 + 8) * LDA + k0 + tig],     ah[f][1], al[f][1]);
            split_tf32(sA[r0 * LDA + k0 + tig + 4],       ah[f][2], al[f][2]);
            split_tf32(sA[(r0 + 8) * LDA + k0 + tig + 4], ah[f][3], al[f][3]);
        }
        #pragma unroll
        for (int nt = 0; nt < NT; nt++) {
            int c0 = n0 + nt * 8 + gid;
            float2 bh2 = *(const float2*)&sBh[c0 * LDB + k0 + 2 * tig];
            float2 bl2 = *(const float2*)&sBl[c0 * LDB + k0 + 2 * tig];
            uint32_t bh[2] = { __float_as_uint(bh2.x), __float_as_uint(bh2.y) };
            uint32_t bl[2] = { __float_as_uint(bl2.x), __float_as_uint(bl2.y) };
            #pragma unroll
            for (int f = 0; f < 2; f++) {
                mma_tf32(acc[f][nt], al[f], bh);
                mma_tf32(acc[f][nt], ah[f], bl);
                mma_tf32(acc[f][nt], ah[f], bh);
            }
        }
    }
}

// ---------------- GEMM: A pre-split paired hi/lo, B paired-transposed hi/lo ----------------
template<int K, int LDA, int NT, int LDB>
__device__ __forceinline__ void gemm_pp(const float* __restrict__ sAh,
                                        const float* __restrict__ sAl,
                                        const float* __restrict__ sBh,
                                        const float* __restrict__ sBl,
                                        int mr, int n0, int lane, float acc[2][NT][4]) {
    int gid = lane >> 2, tig = lane & 3;
    #pragma unroll
    for (int k0 = 0; k0 < K; k0 += 8) {
        uint32_t ah[2][4], al[2][4];
        #pragma unroll
        for (int f = 0; f < 2; f++) {
            int r0 = mr + f * 16 + gid;
            float2 h0 = *(const float2*)&sAh[r0 * LDA + k0 + 2 * tig];
            float2 h1 = *(const float2*)&sAh[(r0 + 8) * LDA + k0 + 2 * tig];
            float2 l0 = *(const float2*)&sAl[r0 * LDA + k0 + 2 * tig];
            float2 l1 = *(const float2*)&sAl[(r0 + 8) * LDA + k0 + 2 * tig];
            ah[f][0] = __float_as_uint(h0.x); ah[f][1] = __float_as_uint(h1.x);
            ah[f][2] = __float_as_uint(h0.y); ah[f][3] = __float_as_uint(h1.y);
            al[f][0] = __float_as_uint(l0.x); al[f][1] = __float_as_uint(l1.x);
            al[f][2] = __float_as_uint(l0.y); al[f][3] = __float_as_uint(l1.y);
        }
        #pragma unroll
        for (int nt = 0; nt < NT; nt++) {
            int c0 = n0 + nt * 8 + gid;
            float2 bh2 = *(const float2*)&sBh[c0 * LDB + k0 + 2 * tig];
            float2 bl2 = *(const float2*)&sBl[c0 * LDB + k0 + 2 * tig];
            uint32_t bh[2] = { __float_as_uint(bh2.x), __float_as_uint(bh2.y) };
            uint32_t bl[2] = { __float_as_uint(bl2.x), __float_as_uint(bl2.y) };
            #pragma unroll
            for (int f = 0; f < 2; f++) {
                mma_tf32(acc[f][nt], al[f], bh);
                mma_tf32(acc[f][nt], ah[f], bl);
                mma_tf32(acc[f][nt], ah[f], bh);
            }
        }
    }
}

// ---------------- edge index decode ----------------
__global__ void cvt_edges_kernel(const int* __restrict__ raw) {
    __shared__ int is64;
    if (threadIdx.x == 0) {
        int odd = 0;
        #pragma unroll 1
        for (int i = 1; i < 512; i += 2) odd |= raw[i];
        is64 = (odd == 0) ? 1 : 0;
    }
    __syncthreads();
    int e = blockIdx.x * blockDim.x + threadIdx.x;
    if (e < EE) {
        if (is64) { g_src[e] = raw[2 * e];        g_tgt[e] = raw[2 * (EE + e)]; }
        else      { g_src[e] = raw[e];            g_tgt[e] = raw[EE + e]; }
    }
}

// ---------------- encoder ----------------
__global__ void enc_kernel(const float* __restrict__ x,
                           const float* __restrict__ w,
                           const float* __restrict__ b) {
    int tid = blockIdx.x * blockDim.x + threadIdx.x;
    int i = tid >> 6, f = tid & 63;
    float acc = b[f];
    #pragma unroll
    for (int k = 0; k < 4; k++) acc = fmaf(x[i * 4 + k], w[k * 64 + f], acc);
    g_h[tid] = acc;
    g_agg[tid] = 0.f;
}

// ================= PQ kernel: [P|Q] = h @ [W1a ; W1b]  (P gets +b1) =================
// smem: sA 128x68 = 8704 ; Bh 128x72 = 9216 ; Bl 9216  -> 108544 B, 2 blocks/SM
#define PQ_A   0
#define PQ_BH  8704
#define PQ_BL  17920
#define PQ_FLOATS 27136
#define PQ_BYTES  (PQ_FLOATS * 4)

__global__ void __launch_bounds__(256) pq_kernel(const float* __restrict__ w1,
                                                 const float* __restrict__ b1) {
    extern __shared__ float sm[];
    float* sA  = sm + PQ_A;
    float* sBh = sm + PQ_BH;
    float* sBl = sm + PQ_BL;
    int tid = threadIdx.x;
    int nb0 = blockIdx.x * 128;

    // stage B' = 64(k) x 128(n) transposed + pair-permuted:
    // n<64 -> W1a[k][n]=w1[k*64+n]; n>=64 -> W1b=w1[(64+k)*64+(n-64)]
    for (int i = tid; i < 8192; i += 256) {
        int k = i >> 7, n = i & 127;
        float w = w1[((n < 64) ? k : (64 + k)) * 64 + (n & 63)];
        uint32_t h, l; split_tf32(w, h, l);
        int pos = n * 72 + (k & ~7) + ((k & 3) << 1) + ((k >> 2) & 1);
        sBh[pos] = __uint_as_float(h);
        sBl[pos] = __uint_as_float(l);
    }
    #pragma unroll
    for (int it = 0; it < 8; it++) {
        int idx = tid + it * 256;
        int row = idx >> 4, f4 = idx & 15;
        float4 v = *(const float4*)&g_h[(nb0 + row) * 64 + f4 * 4];
        *(float4*)&sA[row * 68 + f4 * 4] = v;
    }
    __syncthreads();

    int warp = tid >> 5, lane = tid & 31, gid = lane >> 2, tig = lane & 3;
    int mr = (warp >> 1) * 32, n0 = (warp & 1) * 64;

    float acc[2][8][4] = {};
    gemm_sp<64, 68, 8, 72>(sA, sBh, sBl, mr, n0, lane, acc);

    #pragma unroll
    for (int f = 0; f < 2; f++) {
        int r0 = mr + f * 16 + gid;
        #pragma unroll
        for (int nt = 0; nt < 8; nt++) {
            int col = n0 + nt * 8 + 2 * tig;
            float bb0 = (col < 64) ? __ldg(b1 + col)     : 0.f;
            float bb1 = (col < 64) ? __ldg(b1 + col + 1) : 0.f;
            g_PQ[(nb0 + r0) * 128 + col]         = acc[f][nt][0] + bb0;
            g_PQ[(nb0 + r0) * 128 + col + 1]     = acc[f][nt][1] + bb1;
            g_PQ[(nb0 + r0 + 8) * 128 + col]     = acc[f][nt][2] + bb0;
            g_PQ[(nb0 + r0 + 8) * 128 + col + 1] = acc[f][nt][3] + bb1;
        }
    }
}

// ================= edge kernel: m=relu(P[tgt]+Q[src]) pre-split; out=relu(m@W2+b2); scatter ===
// smem: sMh 128x72, sMl 128x72 (sMl reused as output staging), B2h/B2l 64x72, b2
//       = 27712 floats = 110848 B -> 2 blocks/SM
#define E_MH   0
#define E_ML   9216
#define E_B2H  18432
#define E_B2L  23040
#define E_BI2  27648
#define E_FLOATS 27712
#define E_BYTES  (E_FLOATS * 4)

__global__ void __launch_bounds__(256) edge_mma_kernel(const float* __restrict__ w2,
                                                       const float* __restrict__ b2) {
    extern __shared__ float sm[];
    float* sMh = sm + E_MH;
    float* sMl = sm + E_ML;
    float* sO  = sm + E_ML;    // output staging reuses lo-array (guarded by syncs)
    int tid = threadIdx.x;

    if (blockIdx.x == 0) {
        for (int i = tid; i < NBATCH * NHID; i += 256) { g_sum[i] = 0.f; g_sqs[i] = 0.f; }
    }
    stage_Bt<64, 72>(sm + E_B2H, sm + E_B2L, w2);
    if (tid < 64) sm[E_BI2 + tid] = b2[tid];

    int warp = tid >> 5, lane = tid & 31, gid = lane >> 2, tig = lane & 3;
    int mr = (warp >> 1) * 32, n0 = (warp & 1) * 32;

    for (int tile = blockIdx.x; tile < EE / 128; tile += gridDim.x) {
        int e0 = tile * 128;
        __syncthreads();   // S0: staging visible / prev scatter+gemm reads of sMl,sMh done
        // gather + relu + pre-split into paired layout: 128 rows x 8 k-groups
        #pragma unroll
        for (int it = 0; it < 4; it++) {
            int idx = tid + it * 256;
            int row = idx >> 3, kg = idx & 7;
            int t = g_tgt[e0 + row], s = g_src[e0 + row];
            float4 pa = *(const float4*)&g_PQ[t * 128 + kg * 8];
            float4 pb = *(const float4*)&g_PQ[t * 128 + kg * 8 + 4];
            float4 qa = *(const float4*)&g_PQ[s * 128 + 64 + kg * 8];
            float4 qb = *(const float4*)&g_PQ[s * 128 + 64 + kg * 8 + 4];
            uint32_t h[8], l[8];
            split_tf32(fmaxf(pa.x + qa.x, 0.f), h[0], l[0]);
            split_tf32(fmaxf(pa.y + qa.y, 0.f), h[1], l[1]);
            split_tf32(fmaxf(pa.z + qa.z, 0.f), h[2], l[2]);
            split_tf32(fmaxf(pa.w + qa.w, 0.f), h[3], l[3]);
            split_tf32(fmaxf(pb.x + qb.x, 0.f), h[4], l[4]);
            split_tf32(fmaxf(pb.y + qb.y, 0.f), h[5], l[5]);
            split_tf32(fmaxf(pb.z + qb.z, 0.f), h[6], l[6]);
            split_tf32(fmaxf(pb.w + qb.w, 0.f), h[7], l[7]);
            int base = row * 72 + kg * 8;
            // permuted order within 8-slot block: [k0, k0+4, k0+1, k0+5 | k0+2, k0+6, k0+3, k0+7]
            *(float4*)&sMh[base]     = make_float4(__uint_as_float(h[0]), __uint_as_float(h[4]),
                                                   __uint_as_float(h[1]), __uint_as_float(h[5]));
            *(float4*)&sMh[base + 4] = make_float4(__uint_as_float(h[2]), __uint_as_float(h[6]),
                                                   __uint_as_float(h[3]), __uint_as_float(h[7]));
            *(float4*)&sMl[base]     = make_float4(__uint_as_float(l[0]), __uint_as_float(l[4]),
                                                   __uint_as_float(l[1]), __uint_as_float(l[5]));
            *(float4*)&sMl[base + 4] = make_float4(__uint_as_float(l[2]), __uint_as_float(l[6]),
                                                   __uint_as_float(l[3]), __uint_as_float(l[7]));
        }
        __syncthreads();   // S1
        float acc[2][4][4] = {};
        gemm_pp<64, 72, 4, 72>(sMh, sMl, sm + E_B2H, sm + E_B2L, mr, n0, lane, acc);
        __syncthreads();   // S2: all gemm reads of sMl done before overwrite
        #pragma unroll
        for (int f = 0; f < 2; f++) {
            int r0 = mr + f * 16 + gid;
            #pragma unroll
            for (int nt = 0; nt < 4; nt++) {
                int col = n0 + nt * 8 + 2 * tig;
                float bb0 = sm[E_BI2 + col], bb1 = sm[E_BI2 + col + 1];
                sO[r0 * 72 + col]           = fmaxf(acc[f][nt][0] + bb0, 0.f);
                sO[r0 * 72 + col + 1]       = fmaxf(acc[f][nt][1] + bb1, 0.f);
                sO[(r0 + 8) * 72 + col]     = fmaxf(acc[f][nt][2] + bb0, 0.f);
                sO[(r0 + 8) * 72 + col + 1] = fmaxf(acc[f][nt][3] + bb1, 0.f);
            }
        }
        __syncthreads();   // S3
        #pragma unroll
        for (int it = 0; it < 8; it++) {
            int idx = tid + it * 256;
            int row = idx >> 4, f4 = idx & 15;
            int t = g_tgt[e0 + row];
            float4 v = *(const float4*)&sO[row * 72 + f4 * 4];
            red_add_v4(&g_agg[t * 64 + f4 * 4], v);
        }
    }
}

// ================= node update kernel (K=128 GEMM1, K=64 GEMM2) + fused norm stats ============
// smem: sA 128x132=16896; sM 128x68=8704; B1h/B1l 64x136; B2h/B2l 64x72; biases
//       = 52352 floats = 209408 B -> 1 block/SM
#define U_A    0
#define U_M    16896
#define U_B1H  25600
#define U_B1L  34304
#define U_B2H  43008
#define U_B2L  47616
#define U_BI1  52224
#define U_BI2  52288
#define U_FLOATS 52352
#define U_BYTES  (U_FLOATS * 4)

__global__ void __launch_bounds__(256) upd_mma_kernel(const float* __restrict__ w1,
                                                      const float* __restrict__ b1,
                                                      const float* __restrict__ w2,
                                                      const float* __restrict__ b2) {
    extern __shared__ float sm[];
    float* sA = sm + U_A;
    float* sM = sm + U_M;
    int tid = threadIdx.x;
    stage_Bt<128, 136>(sm + U_B1H, sm + U_B1L, w1);
    stage_Bt<64, 72>(sm + U_B2H, sm + U_B2L, w2);
    if (tid < 64) { sm[U_BI1 + tid] = b1[tid]; sm[U_BI2 + tid] = b2[tid]; }

    int warp = tid >> 5, lane = tid & 31, gid = lane >> 2, tig = lane & 3;
    int mr = (warp >> 1) * 32, n0 = (warp & 1) * 32;
    int nb0 = blockIdx.x * 128;

    #pragma unroll
    for (int it = 0; it < 16; it++) {
        int i = tid + it * 256;
        int e = i >> 5, part = i & 31;
        int node = nb0 + e;
        float4 v;
        if (part < 16) {
            v = *(const float4*)&g_h[node * 64 + part * 4];
        } else {
            float4* ap = (float4*)&g_agg[node * 64 + (part & 15) * 4];
            v = *ap;
            *ap = make_float4(0.f, 0.f, 0.f, 0.f);
        }
        *(float4*)&sA[e * 132 + part * 4] = v;
    }
    __syncthreads();
    float acc[2][4][4] = {};
    gemm_sp<128, 132, 4, 136>(sA, sm + U_B1H, sm + U_B1L, mr, n0, lane, acc);
    #pragma unroll
    for (int f = 0; f < 2; f++) {
        int r0 = mr + f * 16 + gid;
        #pragma unroll
        for (int nt = 0; nt < 4; nt++) {
            int col = n0 + nt * 8 + 2 * tig;
            float bb0 = sm[U_BI1 + col], bb1 = sm[U_BI1 + col + 1];
            sM[r0 * 68 + col]           = fmaxf(acc[f][nt][0] + bb0, 0.f);
            sM[r0 * 68 + col + 1]       = fmaxf(acc[f][nt][1] + bb1, 0.f);
            sM[(r0 + 8) * 68 + col]     = fmaxf(acc[f][nt][2] + bb0, 0.f);
            sM[(r0 + 8) * 68 + col + 1] = fmaxf(acc[f][nt][3] + bb1, 0.f);
        }
    }
    __syncthreads();
    float acc2[2][4][4] = {};
    gemm_sp<64, 68, 4, 72>(sM, sm + U_B2H, sm + U_B2L, mr, n0, lane, acc2);
    #pragma unroll
    for (int f = 0; f < 2; f++) {
        int r0 = mr + f * 16 + gid;
        #pragma unroll
        for (int nt = 0; nt < 4; nt++) {
            int col = n0 + nt * 8 + 2 * tig;
            float bb0 = sm[U_BI2 + col], bb1 = sm[U_BI2 + col + 1];
            sA[r0 * 68 + col]           = fmaxf(acc2[f][nt][0] + bb0, 0.f);
            sA[r0 * 68 + col + 1]       = fmaxf(acc2[f][nt][1] + bb1, 0.f);
            sA[(r0 + 8) * 68 + col]     = fmaxf(acc2[f][nt][2] + bb0, 0.f);
            sA[(r0 + 8) * 68 + col + 1] = fmaxf(acc2[f][nt][3] + bb1, 0.f);
        }
    }
    __syncthreads();
    // store + fused per-feature stats (tile is within one graph: 2048 % 128 == 0)
    int f4 = tid & 15;
    float4 s = make_float4(0.f, 0.f, 0.f, 0.f);
    float4 q = make_float4(0.f, 0.f, 0.f, 0.f);
    #pragma unroll
    for (int it = 0; it < 8; it++) {
        int idx = tid + it * 256;
        int row = idx >> 4;
        float4 v = *(const float4*)&sA[row * 68 + f4 * 4];
        *(float4*)&g_h[(nb0 + row) * 64 + f4 * 4] = v;
        s.x += v.x; s.y += v.y; s.z += v.z; s.w += v.w;
        q.x = fmaf(v.x, v.x, q.x); q.y = fmaf(v.y, v.y, q.y);
        q.z = fmaf(v.z, v.z, q.z); q.w = fmaf(v.w, v.w, q.w);
    }
    int g = nb0 >> 11;
    red_add_v4(&g_sum[g * 64 + f4 * 4], s);
    red_add_v4(&g_sqs[g * 64 + f4 * 4], q);
}

// ---------------- instance norm: coalesced apply ----------------
__global__ void norm_apply_kernel() {
    int g = blockIdx.x >> 3, sl = blockIdx.x & 7;
    int tid = threadIdx.x;
    __shared__ float smean[64], srstd[64];
    if (tid < 64) {
        float mean = g_sum[g * 64 + tid] * (1.f / NSAMPLES);
        float var  = g_sqs[g * 64 + tid] * (1.f / NSAMPLES) - mean * mean;
        smean[tid] = mean;
        srstd[tid] = rsqrtf(var + EPSI);
    }
    __syncthreads();
    int f4 = tid & 15, rc = tid >> 4;
    int row0 = g * NSAMPLES + sl * 256 + rc * 16;
    float4 mn = *(const float4*)&smean[f4 * 4];
    float4 rs = *(const float4*)&srstd[f4 * 4];
    #pragma unroll
    for (int r = 0; r < 16; r++) {
        float4* p = (float4*)&g_h[(row0 + r) * 64 + f4 * 4];
        float4 v = *p;
        v.x = (v.x - mn.x) * rs.x; v.y = (v.y - mn.y) * rs.y;
        v.z = (v.z - mn.z) * rs.z; v.w = (v.w - mn.w) * rs.w;
        *p = v;
    }
}

__global__ void zero_small_kernel() {
    int t = threadIdx.x;
    if (t < NBATCH) { g_t2[t] = 0.f; g_t3[t] = 0.f; }
}

// ---------------- decoder + t2 term ----------------
__global__ void dec_kernel(const float* __restrict__ w, const float* __restrict__ b) {
    int i = blockIdx.x * blockDim.x + threadIdx.x;
    const float* hr = &g_h[i * 64];
    float a0 = b[0], a1 = b[1], a2 = b[2], a3 = b[3];
    #pragma unroll 8
    for (int k = 0; k < 64; k++) {
        float hv = hr[k];
        a0 = fmaf(hv, w[k * 4 + 0], a0);
        a1 = fmaf(hv, w[k * 4 + 1], a1);
        a2 = fmaf(hv, w[k * 4 + 2], a2);
        a3 = fmaf(hv, w[k * 4 + 3], a3);
    }
    a0 = 1.f / (1.f + expf(-a0));
    a1 = 1.f / (1.f + expf(-a1));
    a2 = 1.f / (1.f + expf(-a2));
    a3 = 1.f / (1.f + expf(-a3));
    g_X[i * 4 + 0] = a0; g_X[i * 4 + 1] = a1;
    g_X[i * 4 + 2] = a2; g_X[i * 4 + 3] = a3;
    float pr = (1.f - a0 * a0) * (1.f - a1 * a1) * (1.f - a2 * a2) * (1.f - a3 * a3);
    #pragma unroll
    for (int off = 16; off > 0; off >>= 1)
        pr += __shfl_down_sync(0xffffffffu, pr, off);
    if ((threadIdx.x & 31) == 0) atomicAdd(&g_t2[i >> 11], pr);
}

// ---------------- t3 pairwise term ----------------
__global__ void t3_kernel() {
    int b = blockIdx.x;
    int g = b >> 6, ic = (b >> 2) & 15, jc = b & 3;
    int tid = threadIdx.x;         // 128
    __shared__ float4 sX[512];
    const float4* Xg = (const float4*)&g_X[(g * NSAMPLES) * 4];
    for (int j = tid; j < 512; j += 128) sX[j] = Xg[jc * 512 + j];
    __syncthreads();
    float4 xi = Xg[ic * 128 + tid];
    float acc = 0.f;
    #pragma unroll 4
    for (int j = 0; j < 512; j++) {
        float4 xj = sX[j];
        float p = (1.f - fmaxf(xi.x, xj.x)) * (1.f - fmaxf(xi.y, xj.y)) *
                  (1.f - fmaxf(xi.z, xj.z)) * (1.f - fmaxf(xi.w, xj.w));
        acc += p;
    }
    __shared__ float red[128];
    red[tid] = acc; __syncthreads();
    for (int off = 64; off > 0; off >>= 1) {
        if (tid < off) red[tid] += red[tid + off];
        __syncthreads();
    }
    if (tid == 0) atomicAdd(&g_t3[g], red[0]);
}

// ---------------- emit ----------------
__global__ void emit_kernel(float* __restrict__ out, int out_size) {
    int tid = blockIdx.x * blockDim.x + threadIdx.x;
    float loss = 0.f;
    if (tid == 0) {
        const float t1 = 1.0f / 81.0f;
        #pragma unroll
        for (int g = 0; g < NBATCH; g++) {
            float l = t1 - g_t2[g] * (2.0f / 32768.0f)
                         + g_t3[g] * (1.0f / (2048.f * 2048.f));
            loss += l;
        }
        loss *= (1.0f / NBATCH);
    }
    if (out_size == NN * DIMX) {
        if (tid < NN * DIMX) out[tid] = g_X[tid];
    } else {
        if (tid == 0) out[0] = loss;
        int idx = tid - 1;
        if (idx >= 0 && idx < NN * DIMX && (idx + 1) < out_size) out[1 + idx] = g_X[idx];
    }
}

// ---------------- launch ----------------
extern "C" void kernel_launch(void* const* d_in, const int* in_sizes, int n_in,
                              void* d_out, int out_size) {
    const float* x     = (const float*)d_in[0];
    const int*   eiraw = (const int*)  d_in[1];
    const float* enc_w = (const float*)d_in[2];
    const float* enc_b = (const float*)d_in[3];
    const float* m1_w  = (const float*)d_in[4];
    const float* m1_b  = (const float*)d_in[5];
    const float* m2_w  = (const float*)d_in[6];
    const float* m2_b  = (const float*)d_in[7];
    const float* u1_w  = (const float*)d_in[8];
    const float* u1_b  = (const float*)d_in[9];
    const float* u2_w  = (const float*)d_in[10];
    const float* u2_b  = (const float*)d_in[11];
    const float* dec_w = (const float*)d_in[12];
    const float* dec_b = (const float*)d_in[13];
    float* out = (float*)d_out;

    (void)cudaFuncSetAttribute(pq_kernel,       cudaFuncAttributeMaxDynamicSharedMemorySize, PQ_BYTES);
    (void)cudaFuncSetAttribute(edge_mma_kernel, cudaFuncAttributeMaxDynamicSharedMemorySize, E_BYTES);
    (void)cudaFuncSetAttribute(upd_mma_kernel,  cudaFuncAttributeMaxDynamicSharedMemorySize, U_BYTES);

    cvt_edges_kernel<<<(EE + 255) / 256, 256>>>(eiraw);
    enc_kernel<<<NN * NHID / 256, 256>>>(x, enc_w, enc_b);
    for (int l = 0; l < NLAYERS; l++) {
        pq_kernel<<<NN / 128, 256, PQ_BYTES>>>(m1_w + l * 128 * 64, m1_b + l * 64);
        edge_mma_kernel<<<296, 256, E_BYTES>>>(m2_w + l * 64 * 64, m2_b + l * 64);
        upd_mma_kernel<<<NN / 128, 256, U_BYTES>>>(
            u1_w + l * 128 * 64, u1_b + l * 64, u2_w + l * 64 * 64, u2_b + l * 64);
        norm_apply_kernel<<<64, 256>>>();
    }
    zero_small_kernel<<<1, 32>>>();
    dec_kernel<<<NN / 256, 256>>>(dec_w, dec_b);
    t3_kernel<<<512, 128>>>();
    emit_kernel<<<(NN * DIMX + 1 + 255) / 256, 256>>>(out, out_size);
}

// round 14
// speedup vs baseline: 3.2633x; 1.0464x over previous
#include <cuda_runtime.h>
#include <math.h>
#include <stdint.h>

#define NBATCH   8
#define NSAMPLES 2048
#define DIMX     4
#define NHID     64
#define NLAYERS  3
#define NN       (NBATCH * NSAMPLES)     // 16384 nodes
#define EE       (NN * 16)               // 262144 edges
#define EPSI     1e-5f

// ---------------- static device scratch ----------------
__device__ float g_h[NN * NHID];
__device__ float g_agg[NN * NHID];
__device__ __align__(16) float g_PQ[NN * 128];   // [P|Q] per node (P includes b1)
__device__ __align__(16) float g_X[NN * DIMX];
__device__ int   g_src[EE];
__device__ int   g_tgt[EE];
__device__ float g_t2[NBATCH];
__device__ float g_t3[NBATCH];
__device__ float g_sum[NBATCH * NHID];
__device__ float g_sqs[NBATCH * NHID];

// ---------------- tf32 helpers ----------------
__device__ __forceinline__ void split_tf32(float x, uint32_t& hi, uint32_t& lo) {
    uint32_t h;
    asm("cvt.rna.tf32.f32 %0, %1;" : "=r"(h) : "f"(x));
    float l = x - __uint_as_float(h);
    uint32_t lr;
    asm("cvt.rna.tf32.f32 %0, %1;" : "=r"(lr) : "f"(l));
    hi = h; lo = lr;
}

__device__ __forceinline__ void mma_tf32(float c[4], const uint32_t a[4], const uint32_t b[2]) {
    asm volatile(
        "mma.sync.aligned.m16n8k8.row.col.f32.tf32.tf32.f32 "
        "{%0,%1,%2,%3}, {%4,%5,%6,%7}, {%8,%9}, {%0,%1,%2,%3};"
        : "+f"(c[0]), "+f"(c[1]), "+f"(c[2]), "+f"(c[3])
        : "r"(a[0]), "r"(a[1]), "r"(a[2]), "r"(a[3]), "r"(b[0]), "r"(b[1]));
}

__device__ __forceinline__ void red_add_v4(float* p, float4 v) {
    asm volatile("red.global.add.v4.f32 [%0], {%1,%2,%3,%4};"
                 :: "l"(p), "f"(v.x), "f"(v.y), "f"(v.z), "f"(v.w) : "memory");
}

__device__ __forceinline__ void red_add_v2(float* p, float a, float b) {
    asm volatile("red.global.add.v2.f32 [%0], {%1,%2};"
                 :: "l"(p), "f"(a), "f"(b) : "memory");
}

// ---------------- paired-transposed B staging ----------------
// w: [K][64] row-major. dst: [64 n][LDB] with k-pair permute: within each 8-k block,
// slot = 2*(k&3) + ((k>>2)&1), so (k+tig, k+tig+4) is one float2 at k0+2*tig.
template<int K, int LDB>
__device__ __forceinline__ void stage_Bt(float* dh, float* dl, const float* __restrict__ w) {
    int tid = threadIdx.x;
    for (int i = tid; i < K * 64; i += 256) {
        int k = i >> 6, n = i & 63;
        uint32_t h, l; split_tf32(w[i], h, l);
        int pos = n * LDB + (k & ~7) + ((k & 3) << 1) + ((k >> 2) & 1);
        dh[pos] = __uint_as_float(h);
        dl[pos] = __uint_as_float(l);
    }
}

// ---------------- GEMM: A fp32 (split in loop), B paired-transposed hi/lo ----------------
template<int K, int LDA, int NT, int LDB>
__device__ __forceinline__ void gemm_sp(const float* __restrict__ sA,
                                        const float* __restrict__ sBh,
                                        const float* __restrict__ sBl,
                                        int mr, int n0, int lane, float acc[2][NT][4]) {
    int gid = lane >> 2, tig = lane & 3;
    #pragma unroll
    for (int k0 = 0; k0 < K; k0 += 8) {
        uint32_t ah[2][4], al[2][4];
        #pragma unroll
        for (int f = 0; f < 2; f++) {
            int r0 = mr + f * 16 + gid;
            split_tf32(sA[r0 * LDA + k0 + tig],           ah[f][0], al[f][0]);
            split_tf32(sA[(r0 + 8) * LDA + k0 + tig],     ah[f][1], al[f][1]);
            split_tf32(sA[r0 * LDA + k0 + tig + 4],       ah[f][2], al[f][2]);
            split_tf32(sA[(r0 + 8) * LDA + k0 + tig + 4], ah[f][3], al[f][3]);
        }
        #pragma unroll
        for (int nt = 0; nt < NT; nt++) {
            int c0 = n0 + nt * 8 + gid;
            float2 bh2 = *(const float2*)&sBh[c0 * LDB + k0 + 2 * tig];
            float2 bl2 = *(const float2*)&sBl[c0 * LDB + k0 + 2 * tig];
            uint32_t bh[2] = { __float_as_uint(bh2.x), __float_as_uint(bh2.y) };
            uint32_t bl[2] = { __float_as_uint(bl2.x), __float_as_uint(bl2.y) };
            #pragma unroll
            for (int f = 0; f < 2; f++) {
                mma_tf32(acc[f][nt], al[f], bh);
                mma_tf32(acc[f][nt], ah[f], bl);
                mma_tf32(acc[f][nt], ah[f], bh);
            }
        }
    }
}

// ---------------- GEMM: A pre-split paired hi/lo, B paired-transposed hi/lo ----------------
template<int K, int LDA, int NT, int LDB>
__device__ __forceinline__ void gemm_pp(const float* __restrict__ sAh,
                                        const float* __restrict__ sAl,
                                        const float* __restrict__ sBh,
                                        const float* __restrict__ sBl,
                                        int mr, int n0, int lane, float acc[2][NT][4]) {
    int gid = lane >> 2, tig = lane & 3;
    #pragma unroll
    for (int k0 = 0; k0 < K; k0 += 8) {
        uint32_t ah[2][4], al[2][4];
        #pragma unroll
        for (int f = 0; f < 2; f++) {
            int r0 = mr + f * 16 + gid;
            float2 h0 = *(const float2*)&sAh[r0 * LDA + k0 + 2 * tig];
            float2 h1 = *(const float2*)&sAh[(r0 + 8) * LDA + k0 + 2 * tig];
            float2 l0 = *(const float2*)&sAl[r0 * LDA + k0 + 2 * tig];
            float2 l1 = *(const float2*)&sAl[(r0 + 8) * LDA + k0 + 2 * tig];
            ah[f][0] = __float_as_uint(h0.x); ah[f][1] = __float_as_uint(h1.x);
            ah[f][2] = __float_as_uint(h0.y); ah[f][3] = __float_as_uint(h1.y);
            al[f][0] = __float_as_uint(l0.x); al[f][1] = __float_as_uint(l1.x);
            al[f][2] = __float_as_uint(l0.y); al[f][3] = __float_as_uint(l1.y);
        }
        #pragma unroll
        for (int nt = 0; nt < NT; nt++) {
            int c0 = n0 + nt * 8 + gid;
            float2 bh2 = *(const float2*)&sBh[c0 * LDB + k0 + 2 * tig];
            float2 bl2 = *(const float2*)&sBl[c0 * LDB + k0 + 2 * tig];
            uint32_t bh[2] = { __float_as_uint(bh2.x), __float_as_uint(bh2.y) };
            uint32_t bl[2] = { __float_as_uint(bl2.x), __float_as_uint(bl2.y) };
            #pragma unroll
            for (int f = 0; f < 2; f++) {
                mma_tf32(acc[f][nt], al[f], bh);
                mma_tf32(acc[f][nt], ah[f], bl);
                mma_tf32(acc[f][nt], ah[f], bh);
            }
        }
    }
}

// ---------------- edge index decode (+ t2/t3 zeroing) ----------------
__global__ void cvt_edges_kernel(const int* __restrict__ raw) {
    __shared__ int is64;
    if (blockIdx.x == 0 && threadIdx.x < NBATCH) {
        g_t2[threadIdx.x] = 0.f; g_t3[threadIdx.x] = 0.f;
    }
    if (threadIdx.x == 0) {
        int odd = 0;
        #pragma unroll 1
        for (int i = 1; i < 512; i += 2) odd |= raw[i];
        is64 = (odd == 0) ? 1 : 0;
    }
    __syncthreads();
    int e = blockIdx.x * blockDim.x + threadIdx.x;
    if (e < EE) {
        if (is64) { g_src[e] = raw[2 * e];        g_tgt[e] = raw[2 * (EE + e)]; }
        else      { g_src[e] = raw[e];            g_tgt[e] = raw[EE + e]; }
    }
}

// ---------------- encoder ----------------
__global__ void enc_kernel(const float* __restrict__ x,
                           const float* __restrict__ w,
                           const float* __restrict__ b) {
    int tid = blockIdx.x * blockDim.x + threadIdx.x;
    int i = tid >> 6, f = tid & 63;
    float acc = b[f];
    #pragma unroll
    for (int k = 0; k < 4; k++) acc = fmaf(x[i * 4 + k], w[k * 64 + f], acc);
    g_h[tid] = acc;
    g_agg[tid] = 0.f;
}

// ================= PQ kernel (+optional fused instance-norm apply) =================
// [P|Q] = hn @ [W1a ; W1b] (P gets +b1), where hn = normalized h when do_norm, else h.
// When do_norm, also writes hn back to g_h (consumed by upd later this layer).
// smem: sA 128x68=8704 ; Bh 128x72=9216 ; Bl 9216 ; mean/rstd 128  -> 108.5 KB, 2/SM
#define PQ_A   0
#define PQ_BH  8704
#define PQ_BL  17920
#define PQ_MN  27136
#define PQ_RS  27200
#define PQ_FLOATS 27264
#define PQ_BYTES  (PQ_FLOATS * 4)

__global__ void __launch_bounds__(256) pq_kernel(const float* __restrict__ w1,
                                                 const float* __restrict__ b1,
                                                 int do_norm) {
    extern __shared__ float sm[];
    float* sA  = sm + PQ_A;
    float* sBh = sm + PQ_BH;
    float* sBl = sm + PQ_BL;
    int tid = threadIdx.x;
    int nb0 = blockIdx.x * 128;
    int g = nb0 >> 11;

    // stage B' = 64(k) x 128(n) transposed + pair-permuted
    for (int i = tid; i < 8192; i += 256) {
        int k = i >> 7, n = i & 127;
        float w = w1[((n < 64) ? k : (64 + k)) * 64 + (n & 63)];
        uint32_t h, l; split_tf32(w, h, l);
        int pos = n * 72 + (k & ~7) + ((k & 3) << 1) + ((k >> 2) & 1);
        sBh[pos] = __uint_as_float(h);
        sBl[pos] = __uint_as_float(l);
    }
    if (do_norm && tid < 64) {
        float mean = g_sum[g * 64 + tid] * (1.f / NSAMPLES);
        float var  = g_sqs[g * 64 + tid] * (1.f / NSAMPLES) - mean * mean;
        sm[PQ_MN + tid] = mean;
        sm[PQ_RS + tid] = rsqrtf(var + EPSI);
    }
    __syncthreads();

    #pragma unroll
    for (int it = 0; it < 8; it++) {
        int idx = tid + it * 256;
        int row = idx >> 4, f4 = idx & 15;
        float4 v = *(const float4*)&g_h[(nb0 + row) * 64 + f4 * 4];
        if (do_norm) {
            float4 mn = *(const float4*)&sm[PQ_MN + f4 * 4];
            float4 rs = *(const float4*)&sm[PQ_RS + f4 * 4];
            v.x = (v.x - mn.x) * rs.x; v.y = (v.y - mn.y) * rs.y;
            v.z = (v.z - mn.z) * rs.z; v.w = (v.w - mn.w) * rs.w;
            *(float4*)&g_h[(nb0 + row) * 64 + f4 * 4] = v;   // materialize normalized h
        }
        *(float4*)&sA[row * 68 + f4 * 4] = v;
    }
    __syncthreads();

    int warp = tid >> 5, lane = tid & 31, gid = lane >> 2, tig = lane & 3;
    int mr = (warp >> 1) * 32, n0 = (warp & 1) * 64;

    float acc[2][8][4] = {};
    gemm_sp<64, 68, 8, 72>(sA, sBh, sBl, mr, n0, lane, acc);

    #pragma unroll
    for (int f = 0; f < 2; f++) {
        int r0 = mr + f * 16 + gid;
        #pragma unroll
        for (int nt = 0; nt < 8; nt++) {
            int col = n0 + nt * 8 + 2 * tig;
            float bb0 = (col < 64) ? __ldg(b1 + col)     : 0.f;
            float bb1 = (col < 64) ? __ldg(b1 + col + 1) : 0.f;
            g_PQ[(nb0 + r0) * 128 + col]         = acc[f][nt][0] + bb0;
            g_PQ[(nb0 + r0) * 128 + col + 1]     = acc[f][nt][1] + bb1;
            g_PQ[(nb0 + r0 + 8) * 128 + col]     = acc[f][nt][2] + bb0;
            g_PQ[(nb0 + r0 + 8) * 128 + col + 1] = acc[f][nt][3] + bb1;
        }
    }
}

// ================= edge kernel: m=relu(P[tgt]+Q[src]) pre-split; out=relu(m@W2+b2);
//                  register-direct v2 scatter (no output staging, 2 syncs/tile) =====
// smem: sMh 128x72, sMl 128x72, B2h/B2l 64x72, b2 = 27712 floats = 110848 B -> 2/SM
#define E_MH   0
#define E_ML   9216
#define E_B2H  18432
#define E_B2L  23040
#define E_BI2  27648
#define E_FLOATS 27712
#define E_BYTES  (E_FLOATS * 4)

__global__ void __launch_bounds__(256) edge_mma_kernel(const float* __restrict__ w2,
                                                       const float* __restrict__ b2) {
    extern __shared__ float sm[];
    float* sMh = sm + E_MH;
    float* sMl = sm + E_ML;
    int tid = threadIdx.x;

    if (blockIdx.x == 0) {
        for (int i = tid; i < NBATCH * NHID; i += 256) { g_sum[i] = 0.f; g_sqs[i] = 0.f; }
    }
    stage_Bt<64, 72>(sm + E_B2H, sm + E_B2L, w2);
    if (tid < 64) sm[E_BI2 + tid] = b2[tid];

    int warp = tid >> 5, lane = tid & 31, gid = lane >> 2, tig = lane & 3;
    int mr = (warp >> 1) * 32, n0 = (warp & 1) * 32;

    for (int tile = blockIdx.x; tile < EE / 128; tile += gridDim.x) {
        int e0 = tile * 128;
        __syncthreads();   // staging visible / previous tile's gemm reads complete
        // gather + relu + pre-split into paired layout: 128 rows x 8 k-groups
        #pragma unroll
        for (int it = 0; it < 4; it++) {
            int idx = tid + it * 256;
            int row = idx >> 3, kg = idx & 7;
            int t = g_tgt[e0 + row], s = g_src[e0 + row];
            float4 pa = *(const float4*)&g_PQ[t * 128 + kg * 8];
            float4 pb = *(const float4*)&g_PQ[t * 128 + kg * 8 + 4];
            float4 qa = *(const float4*)&g_PQ[s * 128 + 64 + kg * 8];
            float4 qb = *(const float4*)&g_PQ[s * 128 + 64 + kg * 8 + 4];
            uint32_t h[8], l[8];
            split_tf32(fmaxf(pa.x + qa.x, 0.f), h[0], l[0]);
            split_tf32(fmaxf(pa.y + qa.y, 0.f), h[1], l[1]);
            split_tf32(fmaxf(pa.z + qa.z, 0.f), h[2], l[2]);
            split_tf32(fmaxf(pa.w + qa.w, 0.f), h[3], l[3]);
            split_tf32(fmaxf(pb.x + qb.x, 0.f), h[4], l[4]);
            split_tf32(fmaxf(pb.y + qb.y, 0.f), h[5], l[5]);
            split_tf32(fmaxf(pb.z + qb.z, 0.f), h[6], l[6]);
            split_tf32(fmaxf(pb.w + qb.w, 0.f), h[7], l[7]);
            int base = row * 72 + kg * 8;
            *(float4*)&sMh[base]     = make_float4(__uint_as_float(h[0]), __uint_as_float(h[4]),
                                                   __uint_as_float(h[1]), __uint_as_float(h[5]));
            *(float4*)&sMh[base + 4] = make_float4(__uint_as_float(h[2]), __uint_as_float(h[6]),
                                                   __uint_as_float(h[3]), __uint_as_float(h[7]));
            *(float4*)&sMl[base]     = make_float4(__uint_as_float(l[0]), __uint_as_float(l[4]),
                                                   __uint_as_float(l[1]), __uint_as_float(l[5]));
            *(float4*)&sMl[base + 4] = make_float4(__uint_as_float(l[2]), __uint_as_float(l[6]),
                                                   __uint_as_float(l[3]), __uint_as_float(l[7]));
        }
        __syncthreads();
        float acc[2][4][4] = {};
        gemm_pp<64, 72, 4, 72>(sMh, sMl, sm + E_B2H, sm + E_B2L, mr, n0, lane, acc);
        // register-direct scatter: bias + relu + red.v2 (no smem writes)
        int t0 = g_tgt[e0 + mr + gid];
        int t1 = g_tgt[e0 + mr + gid + 8];
        int t2 = g_tgt[e0 + mr + 16 + gid];
        int t3 = g_tgt[e0 + mr + 24 + gid];
        #pragma unroll
        for (int nt = 0; nt < 4; nt++) {
            int col = n0 + nt * 8 + 2 * tig;
            float bb0 = sm[E_BI2 + col], bb1 = sm[E_BI2 + col + 1];
            red_add_v2(&g_agg[t0 * 64 + col],
                       fmaxf(acc[0][nt][0] + bb0, 0.f), fmaxf(acc[0][nt][1] + bb1, 0.f));
            red_add_v2(&g_agg[t1 * 64 + col],
                       fmaxf(acc[0][nt][2] + bb0, 0.f), fmaxf(acc[0][nt][3] + bb1, 0.f));
            red_add_v2(&g_agg[t2 * 64 + col],
                       fmaxf(acc[1][nt][0] + bb0, 0.f), fmaxf(acc[1][nt][1] + bb1, 0.f));
            red_add_v2(&g_agg[t3 * 64 + col],
                       fmaxf(acc[1][nt][2] + bb0, 0.f), fmaxf(acc[1][nt][3] + bb1, 0.f));
        }
    }
}

// ================= node update kernel (K=128 GEMM1, K=64 GEMM2) + fused norm stats ============
#define U_A    0
#define U_M    16896
#define U_B1H  25600
#define U_B1L  34304
#define U_B2H  43008
#define U_B2L  47616
#define U_BI1  52224
#define U_BI2  52288
#define U_FLOATS 52352
#define U_BYTES  (U_FLOATS * 4)

__global__ void __launch_bounds__(256) upd_mma_kernel(const float* __restrict__ w1,
                                                      const float* __restrict__ b1,
                                                      const float* __restrict__ w2,
                                                      const float* __restrict__ b2) {
    extern __shared__ float sm[];
    float* sA = sm + U_A;
    float* sM = sm + U_M;
    int tid = threadIdx.x;
    stage_Bt<128, 136>(sm + U_B1H, sm + U_B1L, w1);
    stage_Bt<64, 72>(sm + U_B2H, sm + U_B2L, w2);
    if (tid < 64) { sm[U_BI1 + tid] = b1[tid]; sm[U_BI2 + tid] = b2[tid]; }

    int warp = tid >> 5, lane = tid & 31, gid = lane >> 2, tig = lane & 3;
    int mr = (warp >> 1) * 32, n0 = (warp & 1) * 32;
    int nb0 = blockIdx.x * 128;

    #pragma unroll
    for (int it = 0; it < 16; it++) {
        int i = tid + it * 256;
        int e = i >> 5, part = i & 31;
        int node = nb0 + e;
        float4 v;
        if (part < 16) {
            v = *(const float4*)&g_h[node * 64 + part * 4];
        } else {
            float4* ap = (float4*)&g_agg[node * 64 + (part & 15) * 4];
            v = *ap;
            *ap = make_float4(0.f, 0.f, 0.f, 0.f);
        }
        *(float4*)&sA[e * 132 + part * 4] = v;
    }
    __syncthreads();
    float acc[2][4][4] = {};
    gemm_sp<128, 132, 4, 136>(sA, sm + U_B1H, sm + U_B1L, mr, n0, lane, acc);
    #pragma unroll
    for (int f = 0; f < 2; f++) {
        int r0 = mr + f * 16 + gid;
        #pragma unroll
        for (int nt = 0; nt < 4; nt++) {
            int col = n0 + nt * 8 + 2 * tig;
            float bb0 = sm[U_BI1 + col], bb1 = sm[U_BI1 + col + 1];
            sM[r0 * 68 + col]           = fmaxf(acc[f][nt][0] + bb0, 0.f);
            sM[r0 * 68 + col + 1]       = fmaxf(acc[f][nt][1] + bb1, 0.f);
            sM[(r0 + 8) * 68 + col]     = fmaxf(acc[f][nt][2] + bb0, 0.f);
            sM[(r0 + 8) * 68 + col + 1] = fmaxf(acc[f][nt][3] + bb1, 0.f);
        }
    }
    __syncthreads();
    float acc2[2][4][4] = {};
    gemm_sp<64, 68, 4, 72>(sM, sm + U_B2H, sm + U_B2L, mr, n0, lane, acc2);
    #pragma unroll
    for (int f = 0; f < 2; f++) {
        int r0 = mr + f * 16 + gid;
        #pragma unroll
        for (int nt = 0; nt < 4; nt++) {
            int col = n0 + nt * 8 + 2 * tig;
            float bb0 = sm[U_BI2 + col], bb1 = sm[U_BI2 + col + 1];
            sA[r0 * 68 + col]           = fmaxf(acc2[f][nt][0] + bb0, 0.f);
            sA[r0 * 68 + col + 1]       = fmaxf(acc2[f][nt][1] + bb1, 0.f);
            sA[(r0 + 8) * 68 + col]     = fmaxf(acc2[f][nt][2] + bb0, 0.f);
            sA[(r0 + 8) * 68 + col + 1] = fmaxf(acc2[f][nt][3] + bb1, 0.f);
        }
    }
    __syncthreads();
    // store + fused per-feature stats (tile is within one graph: 2048 % 128 == 0)
    int f4 = tid & 15;
    float4 s = make_float4(0.f, 0.f, 0.f, 0.f);
    float4 q = make_float4(0.f, 0.f, 0.f, 0.f);
    #pragma unroll
    for (int it = 0; it < 8; it++) {
        int idx = tid + it * 256;
        int row = idx >> 4;
        float4 v = *(const float4*)&sA[row * 68 + f4 * 4];
        *(float4*)&g_h[(nb0 + row) * 64 + f4 * 4] = v;
        s.x += v.x; s.y += v.y; s.z += v.z; s.w += v.w;
        q.x = fmaf(v.x, v.x, q.x); q.y = fmaf(v.y, v.y, q.y);
        q.z = fmaf(v.z, v.z, q.z); q.w = fmaf(v.w, v.w, q.w);
    }
    int g = nb0 >> 11;
    red_add_v4(&g_sum[g * 64 + f4 * 4], s);
    red_add_v4(&g_sqs[g * 64 + f4 * 4], q);
}

// ---------------- instance norm: standalone apply (final layer only) ----------------
__global__ void norm_apply_kernel() {
    int g = blockIdx.x >> 3, sl = blockIdx.x & 7;
    int tid = threadIdx.x;
    __shared__ float smean[64], srstd[64];
    if (tid < 64) {
        float mean = g_sum[g * 64 + tid] * (1.f / NSAMPLES);
        float var  = g_sqs[g * 64 + tid] * (1.f / NSAMPLES) - mean * mean;
        smean[tid] = mean;
        srstd[tid] = rsqrtf(var + EPSI);
    }
    __syncthreads();
    int f4 = tid & 15, rc = tid >> 4;
    int row0 = g * NSAMPLES + sl * 256 + rc * 16;
    float4 mn = *(const float4*)&smean[f4 * 4];
    float4 rs = *(const float4*)&srstd[f4 * 4];
    #pragma unroll
    for (int r = 0; r < 16; r++) {
        float4* p = (float4*)&g_h[(row0 + r) * 64 + f4 * 4];
        float4 v = *p;
        v.x = (v.x - mn.x) * rs.x; v.y = (v.y - mn.y) * rs.y;
        v.z = (v.z - mn.z) * rs.z; v.w = (v.w - mn.w) * rs.w;
        *p = v;
    }
}

// ---------------- decoder + t2 term ----------------
__global__ void dec_kernel(const float* __restrict__ w, const float* __restrict__ b) {
    int i = blockIdx.x * blockDim.x + threadIdx.x;
    const float* hr = &g_h[i * 64];
    float a0 = b[0], a1 = b[1], a2 = b[2], a3 = b[3];
    #pragma unroll 8
    for (int k = 0; k < 64; k++) {
        float hv = hr[k];
        a0 = fmaf(hv, w[k * 4 + 0], a0);
        a1 = fmaf(hv, w[k * 4 + 1], a1);
        a2 = fmaf(hv, w[k * 4 + 2], a2);
        a3 = fmaf(hv, w[k * 4 + 3], a3);
    }
    a0 = 1.f / (1.f + expf(-a0));
    a1 = 1.f / (1.f + expf(-a1));
    a2 = 1.f / (1.f + expf(-a2));
    a3 = 1.f / (1.f + expf(-a3));
    g_X[i * 4 + 0] = a0; g_X[i * 4 + 1] = a1;
    g_X[i * 4 + 2] = a2; g_X[i * 4 + 3] = a3;
    float pr = (1.f - a0 * a0) * (1.f - a1 * a1) * (1.f - a2 * a2) * (1.f - a3 * a3);
    #pragma unroll
    for (int off = 16; off > 0; off >>= 1)
        pr += __shfl_down_sync(0xffffffffu, pr, off);
    if ((threadIdx.x & 31) == 0) atomicAdd(&g_t2[i >> 11], pr);
}

// ---------------- t3 pairwise term ----------------
__global__ void t3_kernel() {
    int b = blockIdx.x;
    int g = b >> 6, ic = (b >> 2) & 15, jc = b & 3;
    int tid = threadIdx.x;         // 128
    __shared__ float4 sX[512];
    const float4* Xg = (const float4*)&g_X[(g * NSAMPLES) * 4];
    for (int j = tid; j < 512; j += 128) sX[j] = Xg[jc * 512 + j];
    __syncthreads();
    float4 xi = Xg[ic * 128 + tid];
    float acc = 0.f;
    #pragma unroll 4
    for (int j = 0; j < 512; j++) {
        float4 xj = sX[j];
        float p = (1.f - fmaxf(xi.x, xj.x)) * (1.f - fmaxf(xi.y, xj.y)) *
                  (1.f - fmaxf(xi.z, xj.z)) * (1.f - fmaxf(xi.w, xj.w));
        acc += p;
    }
    __shared__ float red[128];
    red[tid] = acc; __syncthreads();
    for (int off = 64; off > 0; off >>= 1) {
        if (tid < off) red[tid] += red[tid + off];
        __syncthreads();
    }
    if (tid == 0) atomicAdd(&g_t3[g], red[0]);
}

// ---------------- emit ----------------
__global__ void emit_kernel(float* __restrict__ out, int out_size) {
    int tid = blockIdx.x * blockDim.x + threadIdx.x;
    float loss = 0.f;
    if (tid == 0) {
        const float t1 = 1.0f / 81.0f;
        #pragma unroll
        for (int g = 0; g < NBATCH; g++) {
            float l = t1 - g_t2[g] * (2.0f / 32768.0f)
                         + g_t3[g] * (1.0f / (2048.f * 2048.f));
            loss += l;
        }
        loss *= (1.0f / NBATCH);
    }
    if (out_size == NN * DIMX) {
        if (tid < NN * DIMX) out[tid] = g_X[tid];
    } else {
        if (tid == 0) out[0] = loss;
        int idx = tid - 1;
        if (idx >= 0 && idx < NN * DIMX && (idx + 1) < out_size) out[1 + idx] = g_X[idx];
    }
}

// ---------------- launch ----------------
extern "C" void kernel_launch(void* const* d_in, const int* in_sizes, int n_in,
                              void* d_out, int out_size) {
    const float* x     = (const float*)d_in[0];
    const int*   eiraw = (const int*)  d_in[1];
    const float* enc_w = (const float*)d_in[2];
    const float* enc_b = (const float*)d_in[3];
    const float* m1_w  = (const float*)d_in[4];
    const float* m1_b  = (const float*)d_in[5];
    const float* m2_w  = (const float*)d_in[6];
    const float* m2_b  = (const float*)d_in[7];
    const float* u1_w  = (const float*)d_in[8];
    const float* u1_b  = (const float*)d_in[9];
    const float* u2_w  = (const float*)d_in[10];
    const float* u2_b  = (const float*)d_in[11];
    const float* dec_w = (const float*)d_in[12];
    const float* dec_b = (const float*)d_in[13];
    float* out = (float*)d_out;

    (void)cudaFuncSetAttribute(pq_kernel,       cudaFuncAttributeMaxDynamicSharedMemorySize, PQ_BYTES);
    (void)cudaFuncSetAttribute(edge_mma_kernel, cudaFuncAttributeMaxDynamicSharedMemorySize, E_BYTES);
    (void)cudaFuncSetAttribute(upd_mma_kernel,  cudaFuncAttributeMaxDynamicSharedMemorySize, U_BYTES);

    cvt_edges_kernel<<<(EE + 255) / 256, 256>>>(eiraw);
    enc_kernel<<<NN * NHID / 256, 256>>>(x, enc_w, enc_b);
    for (int l = 0; l < NLAYERS; l++) {
        // pq(l) also applies instance-norm of layer l-1 (stats from upd(l-1))
        pq_kernel<<<NN / 128, 256, PQ_BYTES>>>(m1_w + l * 128 * 64, m1_b + l * 64, l > 0);
        edge_mma_kernel<<<296, 256, E_BYTES>>>(m2_w + l * 64 * 64, m2_b + l * 64);
        upd_mma_kernel<<<NN / 128, 256, U_BYTES>>>(
            u1_w + l * 128 * 64, u1_b + l * 64, u2_w + l * 64 * 64, u2_b + l * 64);
    }
    norm_apply_kernel<<<64, 256>>>();   // final layer's norm (for decoder)
    dec_kernel<<<NN / 256, 256>>>(dec_w, dec_b);
    t3_kernel<<<512, 128>>>();
    emit_kernel<<<(NN * DIMX + 1 + 255) / 256, 256>>>(out, out_size);
}